// round 1
// baseline (speedup 1.0000x reference)
#include <cuda_runtime.h>
#include <cstddef>

#define NN 50000
#define NE 800000
#define NG 64

// ---------------- scratch (__device__ globals; no allocation allowed) ----------------
__device__ __align__(16) float d_x0[NN * 64];
__device__ __align__(16) float d_bufA[NN * 128];
__device__ __align__(16) float d_bufB[NN * 128];
__device__ __align__(16) float d_bufC[NN * 128];
__device__ __align__(16) float d_dinv[NN];
__device__ int d_ecnt[NN];
__device__ int d_cursor[NN];
__device__ int d_rowptr[NN + 1];
__device__ int d_csr_src[NE];
__device__ int d_csr_dst[NE];
__device__ __align__(16) float d_csr_norm[NE];
__device__ __align__(16) float d_gmax[NG * 128];
__device__ __align__(16) float d_gsum[NG * 128];
__device__ float d_gcnt[NG];
__device__ __align__(16) float d_g[NG * 256];
__device__ __align__(16) float d_h1[NG * 256];

// ---------------- graph preprocessing ----------------
__global__ void k_init() {
    int i = blockIdx.x * blockDim.x + threadIdx.x;
    if (i < NN) { d_ecnt[i] = 0; d_cursor[i] = 0; }
}

__global__ void k_count(const int* __restrict__ dst) {
    int e = blockIdx.x * blockDim.x + threadIdx.x;
    if (e < NE) atomicAdd(&d_ecnt[dst[e]], 1);
}

__global__ void k_dinv() {
    int i = blockIdx.x * blockDim.x + threadIdx.x;
    if (i < NN) d_dinv[i] = rsqrtf((float)d_ecnt[i] + 1.0f);  // +1 self loop
}

// single-block chunked Hillis-Steele scan: rowptr = exclusive prefix of ecnt
__global__ void k_scan() {
    __shared__ int sdata[1024];
    __shared__ int soff;
    int tid = threadIdx.x;
    if (tid == 0) { soff = 0; d_rowptr[0] = 0; }
    __syncthreads();
    for (int base = 0; base < NN; base += 1024) {
        int i = base + tid;
        sdata[tid] = (i < NN) ? d_ecnt[i] : 0;
        __syncthreads();
        #pragma unroll
        for (int off = 1; off < 1024; off <<= 1) {
            int v = (tid >= off) ? sdata[tid - off] : 0;
            __syncthreads();
            sdata[tid] += v;
            __syncthreads();
        }
        int boff = soff;
        if (i < NN) d_rowptr[i + 1] = boff + sdata[tid];
        __syncthreads();
        if (tid == 0) soff = boff + sdata[1023];
        __syncthreads();
    }
}

__global__ void k_scatter(const int* __restrict__ src, const int* __restrict__ dst) {
    int e = blockIdx.x * blockDim.x + threadIdx.x;
    if (e >= NE) return;
    int s = src[e], d = dst[e];
    int pos = d_rowptr[d] + atomicAdd(&d_cursor[d], 1);
    d_csr_src[pos] = s;
    d_csr_dst[pos] = d;
    d_csr_norm[pos] = d_dinv[s] * d_dinv[d];
}

// ---------------- x0 = [nodes | cat_emb[cats]]  [NN,64] ----------------
__global__ void k_embed(const float* __restrict__ nodes, const int* __restrict__ cats,
                        const float* __restrict__ emb) {
    int t = blockIdx.x * blockDim.x + threadIdx.x;
    if (t >= NN * 16) return;
    int node = t >> 4, j = t & 15;
    float4 v;
    if (j < 8) v = ((const float4*)nodes)[node * 8 + j];
    else       v = ((const float4*)emb)[(size_t)cats[node] * 8 + (j - 8)];
    ((float4*)d_x0)[node * 16 + j] = v;
}

// ---------------- generic GEMM: Y[M,128] = X[M,K] @ (W0 - W1)[K,128] (+bias) ----------------
// 128x128 tile, 8x8 per thread, BK=64 chunks. dyn smem = 64KB.
__global__ void gemm_n128(const float* __restrict__ X, int M, int K,
                          const float* __restrict__ W0, const float* __restrict__ W1,
                          const float* __restrict__ bias,
                          float* __restrict__ Y) {
    extern __shared__ float sm[];
    float* sA = sm;              // [64][128]  k-major
    float* sW = sm + 64 * 128;   // [64][128]
    const int t = threadIdx.x;
    const int row0 = blockIdx.x * 128;
    const int tr = (t >> 4) << 3;
    const int tc = (t & 15) << 3;
    float acc[8][8];
    #pragma unroll
    for (int i = 0; i < 8; i++)
        #pragma unroll
        for (int j = 0; j < 8; j++) acc[i][j] = 0.f;

    for (int k0 = 0; k0 < K; k0 += 64) {
        #pragma unroll
        for (int i = t; i < 2048; i += 256) {         // X tile: 128 rows x 16 float4
            int r = i >> 4, c4 = i & 15;
            float4 v = make_float4(0.f, 0.f, 0.f, 0.f);
            int gr = row0 + r;
            if (gr < M) v = *(const float4*)(X + (size_t)gr * K + k0 + (c4 << 2));
            int kk = c4 << 2;
            sA[(kk + 0) * 128 + r] = v.x;
            sA[(kk + 1) * 128 + r] = v.y;
            sA[(kk + 2) * 128 + r] = v.z;
            sA[(kk + 3) * 128 + r] = v.w;
        }
        #pragma unroll
        for (int i = t; i < 2048; i += 256) {         // W tile: 64 rows x 32 float4
            int r = i >> 5, c4 = i & 31;
            float4 v = *(const float4*)(W0 + (size_t)(k0 + r) * 128 + (c4 << 2));
            if (W1) {
                float4 u = *(const float4*)(W1 + (size_t)(k0 + r) * 128 + (c4 << 2));
                v.x -= u.x; v.y -= u.y; v.z -= u.z; v.w -= u.w;
            }
            *(float4*)(sW + r * 128 + (c4 << 2)) = v;
        }
        __syncthreads();
        #pragma unroll 8
        for (int kk = 0; kk < 64; ++kk) {
            float a[8], w[8];
            *(float4*)(a)     = *(const float4*)(sA + kk * 128 + tr);
            *(float4*)(a + 4) = *(const float4*)(sA + kk * 128 + tr + 4);
            *(float4*)(w)     = *(const float4*)(sW + kk * 128 + tc);
            *(float4*)(w + 4) = *(const float4*)(sW + kk * 128 + tc + 4);
            #pragma unroll
            for (int i = 0; i < 8; i++)
                #pragma unroll
                for (int j = 0; j < 8; j++) acc[i][j] = fmaf(a[i], w[j], acc[i][j]);
        }
        __syncthreads();
    }
    float bv[8];
    if (bias) {
        *(float4*)(bv)     = *(const float4*)(bias + tc);
        *(float4*)(bv + 4) = *(const float4*)(bias + tc + 4);
    } else {
        #pragma unroll
        for (int j = 0; j < 8; j++) bv[j] = 0.f;
    }
    #pragma unroll
    for (int i = 0; i < 8; i++) {
        int gr = row0 + tr + i;
        if (gr < M) {
            float o[8];
            #pragma unroll
            for (int j = 0; j < 8; j++) o[j] = acc[i][j] + bv[j];
            *(float4*)(Y + (size_t)gr * 128 + tc)     = *(float4*)(o);
            *(float4*)(Y + (size_t)gr * 128 + tc + 4) = *(float4*)(o + 4);
        }
    }
}

// ---------------- GCN aggregation: out = relu(b + h*dinv^2 + sum_csr h[src]*norm) ----------------
__global__ void gcn_agg(const float* __restrict__ H, const float* __restrict__ bias,
                        float* __restrict__ out) {
    int warp = threadIdx.x >> 5;
    int lane = threadIdx.x & 31;
    int node = blockIdx.x * 8 + warp;
    if (node >= NN) return;
    float dv = d_dinv[node];
    float sn = dv * dv;
    float4 acc = ((const float4*)H)[node * 32 + lane];
    acc.x *= sn; acc.y *= sn; acc.z *= sn; acc.w *= sn;
    int beg = d_rowptr[node], end = d_rowptr[node + 1];
    for (int e = beg; e < end; ++e) {
        int s = d_csr_src[e];
        float nm = d_csr_norm[e];
        float4 h = ((const float4*)H)[s * 32 + lane];
        acc.x = fmaf(h.x, nm, acc.x);
        acc.y = fmaf(h.y, nm, acc.y);
        acc.z = fmaf(h.z, nm, acc.z);
        acc.w = fmaf(h.w, nm, acc.w);
    }
    float4 b = ((const float4*)bias)[lane];
    float4 r;
    r.x = fmaxf(acc.x + b.x, 0.f);
    r.y = fmaxf(acc.y + b.y, 0.f);
    r.z = fmaxf(acc.z + b.z, 0.f);
    r.w = fmaxf(acc.w + b.w, 0.f);
    ((float4*)out)[node * 32 + lane] = r;
}

// ---------------- zero a float buffer (float4 granularity) ----------------
__global__ void k_zero(float* __restrict__ p, int n4) {
    int i = blockIdx.x * blockDim.x + threadIdx.x;
    if (i < n4) ((float4*)p)[i] = make_float4(0.f, 0.f, 0.f, 0.f);
}

// ---------------- EdgeConv per-edge MLP + segment-max ----------------
// agg[dst] = max over edges of ( relu(A[dst]+B[src]) @ We2 + be2 ), clamped at 0 (final relu)
__global__ void edge_mlp(const float* __restrict__ A, const float* __restrict__ Bm,
                         const float* __restrict__ We2, const float* __restrict__ be2,
                         float* __restrict__ agg) {
    extern __shared__ float sm[];
    float* sW = sm;                // [128][128] = 64KB
    float* sT = sm + 128 * 128;    // [64][128]  = 32KB
    __shared__ int sDst[64];
    __shared__ int sSrc[64];
    const int t = threadIdx.x;
    const int e0 = blockIdx.x * 64;
    if (t < 64) { sDst[t] = d_csr_dst[e0 + t]; sSrc[t] = d_csr_src[e0 + t]; }
    #pragma unroll
    for (int i = t; i < 4096; i += 256) {     // We2: 128 x 32 float4
        int r = i >> 5, c4 = i & 31;
        *(float4*)(sW + r * 128 + (c4 << 2)) = *(const float4*)(We2 + (size_t)r * 128 + (c4 << 2));
    }
    __syncthreads();
    #pragma unroll
    for (int i = t; i < 2048; i += 256) {     // t = relu(A[dst]+B[src]) : 64 x 32 float4
        int e = i >> 5, c4 = i & 31;
        int d = sDst[e], s = sSrc[e];
        float4 av = *(const float4*)(A  + (size_t)d * 128 + (c4 << 2));
        float4 bv = *(const float4*)(Bm + (size_t)s * 128 + (c4 << 2));
        float4 tv;
        tv.x = fmaxf(av.x + bv.x, 0.f);
        tv.y = fmaxf(av.y + bv.y, 0.f);
        tv.z = fmaxf(av.z + bv.z, 0.f);
        tv.w = fmaxf(av.w + bv.w, 0.f);
        *(float4*)(sT + e * 128 + (c4 << 2)) = tv;
    }
    __syncthreads();

    const int tr = (t >> 4) << 2;   // 4 edges per thread
    const int tc = (t & 15) << 3;   // 8 cols per thread
    float acc[4][8];
    #pragma unroll
    for (int i = 0; i < 4; i++)
        #pragma unroll
        for (int j = 0; j < 8; j++) acc[i][j] = 0.f;
    #pragma unroll 8
    for (int k = 0; k < 128; ++k) {
        float w[8];
        *(float4*)(w)     = *(const float4*)(sW + k * 128 + tc);
        *(float4*)(w + 4) = *(const float4*)(sW + k * 128 + tc + 4);
        float a0 = sT[(tr + 0) * 128 + k];
        float a1 = sT[(tr + 1) * 128 + k];
        float a2 = sT[(tr + 2) * 128 + k];
        float a3 = sT[(tr + 3) * 128 + k];
        #pragma unroll
        for (int j = 0; j < 8; j++) {
            acc[0][j] = fmaf(a0, w[j], acc[0][j]);
            acc[1][j] = fmaf(a1, w[j], acc[1][j]);
            acc[2][j] = fmaf(a2, w[j], acc[2][j]);
            acc[3][j] = fmaf(a3, w[j], acc[3][j]);
        }
    }
    float bv[8];
    *(float4*)(bv)     = *(const float4*)(be2 + tc);
    *(float4*)(bv + 4) = *(const float4*)(be2 + tc + 4);
    // merge same-dst runs (CSR is dst-sorted), then pruned positive-only int atomicMax
    int i = 0;
    while (i < 4) {
        int d = sDst[tr + i];
        int i2 = i + 1;
        while (i2 < 4 && sDst[tr + i2] == d) i2++;
        #pragma unroll
        for (int j = 0; j < 8; j++) {
            float m = acc[i][j];
            for (int q = i + 1; q < i2; q++) m = fmaxf(m, acc[q][j]);
            m += bv[j];
            if (m > 0.f) {
                int* addr = (int*)(agg + (size_t)d * 128 + tc + j);
                float cur = __int_as_float(*(volatile int*)addr);
                if (m > cur) atomicMax(addr, __float_as_int(m));
            }
        }
        i = i2;
    }
}

// ---------------- pooling ----------------
__global__ void k_zero_pool() {
    int i = blockIdx.x * blockDim.x + threadIdx.x;
    if (i < NG * 128) { d_gmax[i] = 0.f; d_gsum[i] = 0.f; }
    if (i < NG) d_gcnt[i] = 0.f;
}

__global__ void k_pool(const int* __restrict__ batch, const float* __restrict__ X) {
    int t = blockIdx.x * blockDim.x + threadIdx.x;
    if (t >= NN * 32) return;
    int node = t >> 5, lane = t & 31;
    int g = batch[node];
    float4 v = ((const float4*)X)[node * 32 + lane];
    int base = g * 128 + (lane << 2);
    if (v.x > 0.f) atomicMax((int*)&d_gmax[base + 0], __float_as_int(v.x));
    if (v.y > 0.f) atomicMax((int*)&d_gmax[base + 1], __float_as_int(v.y));
    if (v.z > 0.f) atomicMax((int*)&d_gmax[base + 2], __float_as_int(v.z));
    if (v.w > 0.f) atomicMax((int*)&d_gmax[base + 3], __float_as_int(v.w));
    atomicAdd(&d_gsum[base + 0], v.x);
    atomicAdd(&d_gsum[base + 1], v.y);
    atomicAdd(&d_gsum[base + 2], v.z);
    atomicAdd(&d_gsum[base + 3], v.w);
    if (lane == 0) atomicAdd(&d_gcnt[g], 1.0f);
}

__global__ void k_pool_fin() {
    int t = blockIdx.x * blockDim.x + threadIdx.x;
    if (t >= NG * 256) return;
    int g = t >> 8, c = t & 255;
    float v;
    if (c < 128) v = d_gmax[g * 128 + c];
    else         v = d_gsum[g * 128 + c - 128] / fmaxf(d_gcnt[g], 1.0f);
    d_g[t] = v;
}

// ---------------- head: out = relu(in[64,256] @ W[256,256] + b) ----------------
__global__ void head_gemm(const float* __restrict__ in, const float* __restrict__ W,
                          const float* __restrict__ b, float* __restrict__ out) {
    __shared__ float srow[256];
    int t = threadIdx.x;
    int g = blockIdx.x;
    srow[t] = in[g * 256 + t];
    __syncthreads();
    float acc = b[t];
    #pragma unroll 8
    for (int k = 0; k < 256; ++k) acc = fmaf(srow[k], W[k * 256 + t], acc);
    out[g * 256 + t] = fmaxf(acc, 0.f);
}

// ---------------- launch ----------------
extern "C" void kernel_launch(void* const* d_in, const int* in_sizes, int n_in,
                              void* d_out, int out_size) {
    const float* nodes   = (const float*)d_in[0];
    const int*   cats    = (const int*)d_in[1];
    const int*   ei      = (const int*)d_in[2];
    const int*   batch   = (const int*)d_in[3];
    const float* cat_emb = (const float*)d_in[4];
    const float* W1  = (const float*)d_in[5];
    const float* b1  = (const float*)d_in[6];
    const float* W2  = (const float*)d_in[7];
    const float* b2  = (const float*)d_in[8];
    const float* W3  = (const float*)d_in[9];
    const float* b3  = (const float*)d_in[10];
    const float* We1 = (const float*)d_in[11];
    const float* be1 = (const float*)d_in[12];
    const float* We2 = (const float*)d_in[13];
    const float* be2 = (const float*)d_in[14];
    const float* Wf1 = (const float*)d_in[15];
    const float* bf1 = (const float*)d_in[16];
    const float* Wf2 = (const float*)d_in[17];
    const float* bf2 = (const float*)d_in[18];
    const int* src = ei;
    const int* dst = ei + NE;
    float* out = (float*)d_out;

    cudaFuncSetAttribute(gemm_n128, cudaFuncAttributeMaxDynamicSharedMemorySize, 65536);
    cudaFuncSetAttribute(edge_mlp,  cudaFuncAttributeMaxDynamicSharedMemorySize, 98304);

    float *bufA, *bufB, *bufC, *x0, *g, *h1;
    cudaGetSymbolAddress((void**)&bufA, d_bufA);
    cudaGetSymbolAddress((void**)&bufB, d_bufB);
    cudaGetSymbolAddress((void**)&bufC, d_bufC);
    cudaGetSymbolAddress((void**)&x0,   d_x0);
    cudaGetSymbolAddress((void**)&g,    d_g);
    cudaGetSymbolAddress((void**)&h1,   d_h1);

    // CSR + norms
    k_init<<<(NN + 255) / 256, 256>>>();
    k_count<<<(NE + 255) / 256, 256>>>(dst);
    k_dinv<<<(NN + 255) / 256, 256>>>();
    k_scan<<<1, 1024>>>();
    k_scatter<<<(NE + 255) / 256, 256>>>(src, dst);

    // x0 = [nodes | emb]
    k_embed<<<(NN * 16 + 255) / 256, 256>>>(nodes, cats, cat_emb);

    const int gg = (NN + 127) / 128;  // 391
    // GCN 1
    gemm_n128<<<gg, 256, 65536>>>(x0, NN, 64, W1, nullptr, nullptr, bufA);
    gcn_agg<<<(NN + 7) / 8, 256>>>(bufA, b1, bufB);
    // GCN 2
    gemm_n128<<<gg, 256, 65536>>>(bufB, NN, 128, W2, nullptr, nullptr, bufA);
    gcn_agg<<<(NN + 7) / 8, 256>>>(bufA, b2, bufB);
    // GCN 3
    gemm_n128<<<gg, 256, 65536>>>(bufB, NN, 128, W3, nullptr, nullptr, bufA);
    gcn_agg<<<(NN + 7) / 8, 256>>>(bufA, b3, bufC);   // x3 -> bufC

    // EdgeConv precompute: A = x3 @ (We1_top - We1_bot) + be1 ; B = x3 @ We1_bot
    gemm_n128<<<gg, 256, 65536>>>(bufC, NN, 128, We1, We1 + 128 * 128, be1, bufA);
    gemm_n128<<<gg, 256, 65536>>>(bufC, NN, 128, We1 + 128 * 128, nullptr, nullptr, bufB);

    // EdgeConv per-edge MLP + segment max (into bufC, init 0; final relu implicit)
    k_zero<<<(NN * 32 + 255) / 256, 256>>>(bufC, NN * 32);
    edge_mlp<<<NE / 64, 256, 98304>>>(bufA, bufB, We2, be2, bufC);

    // pooling
    k_zero_pool<<<(NG * 128 + 255) / 256, 256>>>();
    k_pool<<<(NN * 32 + 255) / 256, 256>>>(batch, bufC);
    k_pool_fin<<<(NG * 256 + 255) / 256, 256>>>();

    // head
    head_gemm<<<NG, 256>>>(g, Wf1, bf1, h1);
    head_gemm<<<NG, 256>>>(h1, Wf2, bf2, out);
}

// round 2
// speedup vs baseline: 1.0742x; 1.0742x over previous
#include <cuda_runtime.h>
#include <cstddef>

#define NN 50000
#define NE 800000
#define NG 64

// ---------------- scratch (__device__ globals; no allocation allowed) ----------------
__device__ __align__(16) float d_x0[NN * 64];
__device__ __align__(16) float d_bufA[NN * 128];
__device__ __align__(16) float d_bufB[NN * 128];
__device__ __align__(16) float d_bufC[NN * 128];
__device__ __align__(16) float d_dinv[NN];
__device__ int d_ecnt[NN];
__device__ int d_cursor[NN];
__device__ int d_rowptr[NN + 1];
__device__ int d_csr_src[NE];
__device__ int d_csr_dst[NE];
__device__ __align__(16) float d_csr_norm[NE];
__device__ __align__(16) float d_gmax[NG * 128];
__device__ __align__(16) float d_gsum[NG * 128];
__device__ float d_gcnt[NG];
__device__ __align__(16) float d_g[NG * 256];
__device__ __align__(16) float d_h1[NG * 256];

// ---------------- packed f32x2 helpers ----------------
__device__ __forceinline__ unsigned long long fma2(unsigned long long a,
                                                   unsigned long long b,
                                                   unsigned long long c) {
    unsigned long long d;
    asm("fma.rn.f32x2 %0, %1, %2, %3;" : "=l"(d) : "l"(a), "l"(b), "l"(c));
    return d;
}
__device__ __forceinline__ unsigned long long dup2(float x) {
    unsigned long long d;
    asm("mov.b64 %0, {%1, %1};" : "=l"(d) : "f"(x));
    return d;
}
__device__ __forceinline__ float2 unpack2(unsigned long long v) {
    float2 r;
    asm("mov.b64 {%0, %1}, %2;" : "=f"(r.x), "=f"(r.y) : "l"(v));
    return r;
}

// ---------------- graph preprocessing ----------------
__global__ void k_init() {
    int i = blockIdx.x * blockDim.x + threadIdx.x;
    if (i < NN) { d_ecnt[i] = 0; d_cursor[i] = 0; }
}

__global__ void k_count(const int* __restrict__ dst) {
    int e = blockIdx.x * blockDim.x + threadIdx.x;
    if (e < NE) atomicAdd(&d_ecnt[dst[e]], 1);
}

__global__ void k_dinv() {
    int i = blockIdx.x * blockDim.x + threadIdx.x;
    if (i < NN) d_dinv[i] = rsqrtf((float)d_ecnt[i] + 1.0f);  // +1 self loop
}

// single block, serial-chunk prefix + one 1024-wide block scan
__global__ void k_scan() {
    __shared__ int ssum[1024];
    const int C = (NN + 1023) / 1024;  // 49
    int t = threadIdx.x;
    int beg = t * C;
    int end = beg + C; if (end > NN) end = NN;
    int s = 0;
    for (int i = beg; i < end; i++) s += d_ecnt[i];
    ssum[t] = s;
    __syncthreads();
    #pragma unroll
    for (int off = 1; off < 1024; off <<= 1) {
        int v = (t >= off) ? ssum[t - off] : 0;
        __syncthreads();
        ssum[t] += v;
        __syncthreads();
    }
    int run = (t ? ssum[t - 1] : 0);
    if (t == 0) d_rowptr[0] = 0;
    for (int i = beg; i < end; i++) { run += d_ecnt[i]; d_rowptr[i + 1] = run; }
}

__global__ void k_scatter(const int* __restrict__ src, const int* __restrict__ dst) {
    int e = blockIdx.x * blockDim.x + threadIdx.x;
    if (e >= NE) return;
    int s = src[e], d = dst[e];
    int pos = d_rowptr[d] + atomicAdd(&d_cursor[d], 1);
    d_csr_src[pos] = s;
    d_csr_dst[pos] = d;
    d_csr_norm[pos] = d_dinv[s] * d_dinv[d];
}

// ---------------- x0 = [nodes | cat_emb[cats]]  [NN,64] ----------------
__global__ void k_embed(const float* __restrict__ nodes, const int* __restrict__ cats,
                        const float* __restrict__ emb) {
    int t = blockIdx.x * blockDim.x + threadIdx.x;
    if (t >= NN * 16) return;
    int node = t >> 4, j = t & 15;
    float4 v;
    if (j < 8) v = ((const float4*)nodes)[node * 8 + j];
    else       v = ((const float4*)emb)[(size_t)cats[node] * 8 + (j - 8)];
    ((float4*)d_x0)[node * 16 + j] = v;
}

// ---------------- GEMM: Y[M,128] = X[M,K] @ (W0 - W1)[K,128] (+bias) ----------------
// 128x128 tile, 512 threads, 4x8 per thread (packed f32x2 along cols), BK=64. dyn smem 64KB.
__global__ void __launch_bounds__(512)
gemm_n128(const float* __restrict__ X, int M, int K,
          const float* __restrict__ W0, const float* __restrict__ W1,
          const float* __restrict__ bias,
          float* __restrict__ Y) {
    extern __shared__ float sm[];
    float* sA = sm;              // [64][128]  k-major
    float* sW = sm + 64 * 128;   // [64][128]
    const int t = threadIdx.x;
    const int row0 = blockIdx.x * 128;
    const int tr = (t >> 4) << 2;   // 4 rows
    const int tc = (t & 15) << 3;   // 8 cols (4 packed)
    unsigned long long acc[4][4];
    #pragma unroll
    for (int i = 0; i < 4; i++)
        #pragma unroll
        for (int j = 0; j < 4; j++) acc[i][j] = 0ULL;

    for (int k0 = 0; k0 < K; k0 += 64) {
        // X tile: conflict-free transposed store (r varies across lanes)
        #pragma unroll
        for (int i = t; i < 2048; i += 512) {
            int r = i & 127, c4 = i >> 7;   // c4 in [0,16)
            float4 v = make_float4(0.f, 0.f, 0.f, 0.f);
            int gr = row0 + r;
            if (gr < M) v = *(const float4*)(X + (size_t)gr * K + k0 + (c4 << 2));
            int kk = c4 << 2;
            sA[(kk + 0) * 128 + r] = v.x;
            sA[(kk + 1) * 128 + r] = v.y;
            sA[(kk + 2) * 128 + r] = v.z;
            sA[(kk + 3) * 128 + r] = v.w;
        }
        // W tile (row-major in k)
        #pragma unroll
        for (int i = t; i < 2048; i += 512) {
            int r = i >> 5, c4 = i & 31;
            float4 v = *(const float4*)(W0 + (size_t)(k0 + r) * 128 + (c4 << 2));
            if (W1) {
                float4 u = *(const float4*)(W1 + (size_t)(k0 + r) * 128 + (c4 << 2));
                v.x -= u.x; v.y -= u.y; v.z -= u.z; v.w -= u.w;
            }
            *(float4*)(sW + r * 128 + (c4 << 2)) = v;
        }
        __syncthreads();
        #pragma unroll 4
        for (int kk = 0; kk < 64; ++kk) {
            float4 av = *(const float4*)(sA + kk * 128 + tr);
            ulonglong2 w0 = *(const ulonglong2*)(sW + kk * 128 + tc);
            ulonglong2 w1 = *(const ulonglong2*)(sW + kk * 128 + tc + 4);
            unsigned long long a0 = dup2(av.x), a1 = dup2(av.y),
                               a2 = dup2(av.z), a3 = dup2(av.w);
            acc[0][0] = fma2(a0, w0.x, acc[0][0]);
            acc[0][1] = fma2(a0, w0.y, acc[0][1]);
            acc[0][2] = fma2(a0, w1.x, acc[0][2]);
            acc[0][3] = fma2(a0, w1.y, acc[0][3]);
            acc[1][0] = fma2(a1, w0.x, acc[1][0]);
            acc[1][1] = fma2(a1, w0.y, acc[1][1]);
            acc[1][2] = fma2(a1, w1.x, acc[1][2]);
            acc[1][3] = fma2(a1, w1.y, acc[1][3]);
            acc[2][0] = fma2(a2, w0.x, acc[2][0]);
            acc[2][1] = fma2(a2, w0.y, acc[2][1]);
            acc[2][2] = fma2(a2, w1.x, acc[2][2]);
            acc[2][3] = fma2(a2, w1.y, acc[2][3]);
            acc[3][0] = fma2(a3, w0.x, acc[3][0]);
            acc[3][1] = fma2(a3, w0.y, acc[3][1]);
            acc[3][2] = fma2(a3, w1.x, acc[3][2]);
            acc[3][3] = fma2(a3, w1.y, acc[3][3]);
        }
        __syncthreads();
    }
    float bv[8];
    if (bias) {
        *(float4*)(bv)     = *(const float4*)(bias + tc);
        *(float4*)(bv + 4) = *(const float4*)(bias + tc + 4);
    } else {
        #pragma unroll
        for (int j = 0; j < 8; j++) bv[j] = 0.f;
    }
    #pragma unroll
    for (int i = 0; i < 4; i++) {
        int gr = row0 + tr + i;
        if (gr < M) {
            float o[8];
            #pragma unroll
            for (int j = 0; j < 4; j++) {
                float2 f = unpack2(acc[i][j]);
                o[2 * j]     = f.x + bv[2 * j];
                o[2 * j + 1] = f.y + bv[2 * j + 1];
            }
            *(float4*)(Y + (size_t)gr * 128 + tc)     = *(float4*)(o);
            *(float4*)(Y + (size_t)gr * 128 + tc + 4) = *(float4*)(o + 4);
        }
    }
}

// ---------------- GCN aggregation: out = relu(b + h*dinv^2 + sum_csr h[src]*norm) ----------------
__global__ void gcn_agg(const float* __restrict__ H, const float* __restrict__ bias,
                        float* __restrict__ out) {
    int warp = threadIdx.x >> 5;
    int lane = threadIdx.x & 31;
    int node = blockIdx.x * 8 + warp;
    if (node >= NN) return;
    float dv = d_dinv[node];
    float sn = dv * dv;
    float4 acc = ((const float4*)H)[node * 32 + lane];
    acc.x *= sn; acc.y *= sn; acc.z *= sn; acc.w *= sn;
    int beg = d_rowptr[node], end = d_rowptr[node + 1];
    int e = beg;
    for (; e + 1 < end; e += 2) {
        int s0 = d_csr_src[e], s1 = d_csr_src[e + 1];
        float n0 = d_csr_norm[e], n1 = d_csr_norm[e + 1];
        float4 h0 = ((const float4*)H)[s0 * 32 + lane];
        float4 h1 = ((const float4*)H)[s1 * 32 + lane];
        acc.x = fmaf(h0.x, n0, acc.x); acc.y = fmaf(h0.y, n0, acc.y);
        acc.z = fmaf(h0.z, n0, acc.z); acc.w = fmaf(h0.w, n0, acc.w);
        acc.x = fmaf(h1.x, n1, acc.x); acc.y = fmaf(h1.y, n1, acc.y);
        acc.z = fmaf(h1.z, n1, acc.z); acc.w = fmaf(h1.w, n1, acc.w);
    }
    if (e < end) {
        int s = d_csr_src[e];
        float nm = d_csr_norm[e];
        float4 h = ((const float4*)H)[s * 32 + lane];
        acc.x = fmaf(h.x, nm, acc.x); acc.y = fmaf(h.y, nm, acc.y);
        acc.z = fmaf(h.z, nm, acc.z); acc.w = fmaf(h.w, nm, acc.w);
    }
    float4 b = ((const float4*)bias)[lane];
    float4 r;
    r.x = fmaxf(acc.x + b.x, 0.f);
    r.y = fmaxf(acc.y + b.y, 0.f);
    r.z = fmaxf(acc.z + b.z, 0.f);
    r.w = fmaxf(acc.w + b.w, 0.f);
    ((float4*)out)[node * 32 + lane] = r;
}

// ---------------- zero a float buffer (float4 granularity) ----------------
__global__ void k_zero(float* __restrict__ p, int n4) {
    int i = blockIdx.x * blockDim.x + threadIdx.x;
    if (i < n4) ((float4*)p)[i] = make_float4(0.f, 0.f, 0.f, 0.f);
}

// ---------------- EdgeConv per-edge MLP + segment-max ----------------
// 128 edges/block, 512 threads. agg[dst] = max_e( relu(A[dst]+B[src]) @ We2 + be2 ), init 0.
__global__ void __launch_bounds__(512)
edge_mlp(const float* __restrict__ A, const float* __restrict__ Bm,
         const float* __restrict__ We2, const float* __restrict__ be2,
         float* __restrict__ agg) {
    extern __shared__ float sm[];
    float* sW = sm;                // [128][128] = 64KB
    float* sT = sm + 128 * 128;    // [128][128] k-major = 64KB
    __shared__ int sDst[128];
    __shared__ int sSrc[128];
    const int t = threadIdx.x;
    const int e0 = blockIdx.x * 128;
    if (t < 128) { sDst[t] = d_csr_dst[e0 + t]; sSrc[t] = d_csr_src[e0 + t]; }
    #pragma unroll
    for (int i = t; i < 4096; i += 512) {     // We2: 128 x 32 float4
        int r = i >> 5, c4 = i & 31;
        *(float4*)(sW + r * 128 + (c4 << 2)) = *(const float4*)(We2 + (size_t)r * 128 + (c4 << 2));
    }
    __syncthreads();
    // gather t = relu(A[dst]+B[src]) into k-major sT (conflict-free stores)
    {
        int e = t & 127;
        int d = sDst[e], s = sSrc[e];
        const float4* Ad = (const float4*)(A  + (size_t)d * 128);
        const float4* Bs = (const float4*)(Bm + (size_t)s * 128);
        #pragma unroll
        for (int c4 = (t >> 7); c4 < 32; c4 += 4) {
            float4 av = Ad[c4];
            float4 bv = Bs[c4];
            int kk = c4 << 2;
            sT[(kk + 0) * 128 + e] = fmaxf(av.x + bv.x, 0.f);
            sT[(kk + 1) * 128 + e] = fmaxf(av.y + bv.y, 0.f);
            sT[(kk + 2) * 128 + e] = fmaxf(av.z + bv.z, 0.f);
            sT[(kk + 3) * 128 + e] = fmaxf(av.w + bv.w, 0.f);
        }
    }
    __syncthreads();

    const int tr = (t >> 4) << 2;   // 4 edges
    const int tc = (t & 15) << 3;   // 8 cols (4 packed)
    unsigned long long acc[4][4];
    #pragma unroll
    for (int i = 0; i < 4; i++)
        #pragma unroll
        for (int j = 0; j < 4; j++) acc[i][j] = 0ULL;
    #pragma unroll 4
    for (int k = 0; k < 128; ++k) {
        float4 av = *(const float4*)(sT + k * 128 + tr);
        ulonglong2 w0 = *(const ulonglong2*)(sW + k * 128 + tc);
        ulonglong2 w1 = *(const ulonglong2*)(sW + k * 128 + tc + 4);
        unsigned long long a0 = dup2(av.x), a1 = dup2(av.y),
                           a2 = dup2(av.z), a3 = dup2(av.w);
        acc[0][0] = fma2(a0, w0.x, acc[0][0]);
        acc[0][1] = fma2(a0, w0.y, acc[0][1]);
        acc[0][2] = fma2(a0, w1.x, acc[0][2]);
        acc[0][3] = fma2(a0, w1.y, acc[0][3]);
        acc[1][0] = fma2(a1, w0.x, acc[1][0]);
        acc[1][1] = fma2(a1, w0.y, acc[1][1]);
        acc[1][2] = fma2(a1, w1.x, acc[1][2]);
        acc[1][3] = fma2(a1, w1.y, acc[1][3]);
        acc[2][0] = fma2(a2, w0.x, acc[2][0]);
        acc[2][1] = fma2(a2, w0.y, acc[2][1]);
        acc[2][2] = fma2(a2, w1.x, acc[2][2]);
        acc[2][3] = fma2(a2, w1.y, acc[2][3]);
        acc[3][0] = fma2(a3, w0.x, acc[3][0]);
        acc[3][1] = fma2(a3, w0.y, acc[3][1]);
        acc[3][2] = fma2(a3, w1.x, acc[3][2]);
        acc[3][3] = fma2(a3, w1.y, acc[3][3]);
    }
    float res[4][8];
    float bv[8];
    *(float4*)(bv)     = *(const float4*)(be2 + tc);
    *(float4*)(bv + 4) = *(const float4*)(be2 + tc + 4);
    #pragma unroll
    for (int i = 0; i < 4; i++)
        #pragma unroll
        for (int j = 0; j < 4; j++) {
            float2 f = unpack2(acc[i][j]);
            res[i][2 * j]     = f.x + bv[2 * j];
            res[i][2 * j + 1] = f.y + bv[2 * j + 1];
        }
    // merge same-dst runs (CSR is dst-sorted), pruned positive-only int atomicMax
    int i = 0;
    while (i < 4) {
        int d = sDst[tr + i];
        int i2 = i + 1;
        while (i2 < 4 && sDst[tr + i2] == d) i2++;
        #pragma unroll
        for (int j = 0; j < 8; j++) {
            float m = res[i][j];
            for (int q = i + 1; q < i2; q++) m = fmaxf(m, res[q][j]);
            if (m > 0.f) {
                int* addr = (int*)(agg + (size_t)d * 128 + tc + j);
                float cur = __int_as_float(*(volatile int*)addr);
                if (m > cur) atomicMax(addr, __float_as_int(m));
            }
        }
        i = i2;
    }
}

// ---------------- pooling ----------------
__global__ void k_zero_pool() {
    int i = blockIdx.x * blockDim.x + threadIdx.x;
    if (i < NG * 128) { d_gmax[i] = 0.f; d_gsum[i] = 0.f; }
    if (i < NG) d_gcnt[i] = 0.f;
}

__global__ void k_pool(const int* __restrict__ batch, const float* __restrict__ X) {
    int t = blockIdx.x * blockDim.x + threadIdx.x;
    if (t >= NN * 32) return;
    int node = t >> 5, lane = t & 31;
    int g = batch[node];
    float4 v = ((const float4*)X)[node * 32 + lane];
    int base = g * 128 + (lane << 2);
    if (v.x > 0.f) atomicMax((int*)&d_gmax[base + 0], __float_as_int(v.x));
    if (v.y > 0.f) atomicMax((int*)&d_gmax[base + 1], __float_as_int(v.y));
    if (v.z > 0.f) atomicMax((int*)&d_gmax[base + 2], __float_as_int(v.z));
    if (v.w > 0.f) atomicMax((int*)&d_gmax[base + 3], __float_as_int(v.w));
    atomicAdd(&d_gsum[base + 0], v.x);
    atomicAdd(&d_gsum[base + 1], v.y);
    atomicAdd(&d_gsum[base + 2], v.z);
    atomicAdd(&d_gsum[base + 3], v.w);
    if (lane == 0) atomicAdd(&d_gcnt[g], 1.0f);
}

__global__ void k_pool_fin() {
    int t = blockIdx.x * blockDim.x + threadIdx.x;
    if (t >= NG * 256) return;
    int g = t >> 8, c = t & 255;
    float v;
    if (c < 128) v = d_gmax[g * 128 + c];
    else         v = d_gsum[g * 128 + c - 128] / fmaxf(d_gcnt[g], 1.0f);
    d_g[t] = v;
}

// ---------------- head: out = relu(in[64,256] @ W[256,256] + b) ----------------
__global__ void head_gemm(const float* __restrict__ in, const float* __restrict__ W,
                          const float* __restrict__ b, float* __restrict__ out) {
    __shared__ float srow[256];
    int t = threadIdx.x;
    int g = blockIdx.x;
    srow[t] = in[g * 256 + t];
    __syncthreads();
    float acc = b[t];
    #pragma unroll 8
    for (int k = 0; k < 256; ++k) acc = fmaf(srow[k], W[k * 256 + t], acc);
    out[g * 256 + t] = fmaxf(acc, 0.f);
}

// ---------------- launch ----------------
extern "C" void kernel_launch(void* const* d_in, const int* in_sizes, int n_in,
                              void* d_out, int out_size) {
    const float* nodes   = (const float*)d_in[0];
    const int*   cats    = (const int*)d_in[1];
    const int*   ei      = (const int*)d_in[2];
    const int*   batch   = (const int*)d_in[3];
    const float* cat_emb = (const float*)d_in[4];
    const float* W1  = (const float*)d_in[5];
    const float* b1  = (const float*)d_in[6];
    const float* W2  = (const float*)d_in[7];
    const float* b2  = (const float*)d_in[8];
    const float* W3  = (const float*)d_in[9];
    const float* b3  = (const float*)d_in[10];
    const float* We1 = (const float*)d_in[11];
    const float* be1 = (const float*)d_in[12];
    const float* We2 = (const float*)d_in[13];
    const float* be2 = (const float*)d_in[14];
    const float* Wf1 = (const float*)d_in[15];
    const float* bf1 = (const float*)d_in[16];
    const float* Wf2 = (const float*)d_in[17];
    const float* bf2 = (const float*)d_in[18];
    const int* src = ei;
    const int* dst = ei + NE;
    float* out = (float*)d_out;

    cudaFuncSetAttribute(gemm_n128, cudaFuncAttributeMaxDynamicSharedMemorySize, 65536);
    cudaFuncSetAttribute(edge_mlp,  cudaFuncAttributeMaxDynamicSharedMemorySize, 131072);

    float *bufA, *bufB, *bufC, *x0, *g, *h1;
    cudaGetSymbolAddress((void**)&bufA, d_bufA);
    cudaGetSymbolAddress((void**)&bufB, d_bufB);
    cudaGetSymbolAddress((void**)&bufC, d_bufC);
    cudaGetSymbolAddress((void**)&x0,   d_x0);
    cudaGetSymbolAddress((void**)&g,    d_g);
    cudaGetSymbolAddress((void**)&h1,   d_h1);

    // CSR + norms
    k_init<<<(NN + 255) / 256, 256>>>();
    k_count<<<(NE + 255) / 256, 256>>>(dst);
    k_dinv<<<(NN + 255) / 256, 256>>>();
    k_scan<<<1, 1024>>>();
    k_scatter<<<(NE + 255) / 256, 256>>>(src, dst);

    // x0 = [nodes | emb]
    k_embed<<<(NN * 16 + 255) / 256, 256>>>(nodes, cats, cat_emb);

    const int gg = (NN + 127) / 128;  // 391
    // GCN 1
    gemm_n128<<<gg, 512, 65536>>>(x0, NN, 64, W1, nullptr, nullptr, bufA);
    gcn_agg<<<(NN + 7) / 8, 256>>>(bufA, b1, bufB);
    // GCN 2
    gemm_n128<<<gg, 512, 65536>>>(bufB, NN, 128, W2, nullptr, nullptr, bufA);
    gcn_agg<<<(NN + 7) / 8, 256>>>(bufA, b2, bufB);
    // GCN 3
    gemm_n128<<<gg, 512, 65536>>>(bufB, NN, 128, W3, nullptr, nullptr, bufA);
    gcn_agg<<<(NN + 7) / 8, 256>>>(bufA, b3, bufC);   // x3 -> bufC

    // EdgeConv precompute: A = x3 @ (We1_top - We1_bot) + be1 ; B = x3 @ We1_bot
    gemm_n128<<<gg, 512, 65536>>>(bufC, NN, 128, We1, We1 + 128 * 128, be1, bufA);
    gemm_n128<<<gg, 512, 65536>>>(bufC, NN, 128, We1 + 128 * 128, nullptr, nullptr, bufB);

    // EdgeConv per-edge MLP + segment max (into bufC, init 0; final relu implicit)
    k_zero<<<(NN * 32 + 255) / 256, 256>>>(bufC, NN * 32);
    edge_mlp<<<NE / 128, 512, 131072>>>(bufA, bufB, We2, be2, bufC);

    // pooling
    k_zero_pool<<<(NG * 128 + 255) / 256, 256>>>();
    k_pool<<<(NN * 32 + 255) / 256, 256>>>(batch, bufC);
    k_pool_fin<<<(NG * 256 + 255) / 256, 256>>>();

    // head
    head_gemm<<<NG, 256>>>(g, Wf1, bf1, h1);
    head_gemm<<<NG, 256>>>(h1, Wf2, bf2, out);
}

// round 3
// speedup vs baseline: 1.4749x; 1.3731x over previous
#include <cuda_runtime.h>
#include <cstddef>

#define NN 50000
#define NE 800000
#define NG 64
#define NB 196   // ceil(NN/256)

// ---------------- scratch (__device__ globals; no allocation allowed) ----------------
__device__ __align__(16) float d_x0[NN * 64];
__device__ __align__(16) float d_bufA[NN * 128];
__device__ __align__(16) float d_bufB[NN * 128];
__device__ __align__(16) float d_bufC[NN * 128];
__device__ __align__(16) float d_dinv[NN];
__device__ int d_ecnt[NN];
__device__ int d_cursor[NN];
__device__ int d_rowptr[NN + 1];
__device__ int d_bsum[256];
__device__ int d_boff[256];
__device__ int d_csr_src[NE];
__device__ int d_csr_dst[NE];
__device__ __align__(16) float d_csr_norm[NE];
__device__ __align__(16) float d_gmax[NG * 128];
__device__ __align__(16) float d_gsum[NG * 128];
__device__ float d_gcnt[NG];
__device__ __align__(16) float d_g[NG * 256];
__device__ __align__(16) float d_h1[NG * 256];

// ---------------- packed f32x2 helpers ----------------
__device__ __forceinline__ unsigned long long fma2(unsigned long long a,
                                                   unsigned long long b,
                                                   unsigned long long c) {
    unsigned long long d;
    asm("fma.rn.f32x2 %0, %1, %2, %3;" : "=l"(d) : "l"(a), "l"(b), "l"(c));
    return d;
}
__device__ __forceinline__ unsigned long long dup2(float x) {
    unsigned long long d;
    asm("mov.b64 %0, {%1, %1};" : "=l"(d) : "f"(x));
    return d;
}
__device__ __forceinline__ float2 unpack2(unsigned long long v) {
    float2 r;
    asm("mov.b64 {%0, %1}, %2;" : "=f"(r.x), "=f"(r.y) : "l"(v));
    return r;
}

// ---------------- graph preprocessing ----------------
__global__ void k_init() {
    int i = blockIdx.x * blockDim.x + threadIdx.x;
    if (i < NN) { d_ecnt[i] = 0; d_cursor[i] = 0; }
}

__global__ void k_count(const int* __restrict__ dst) {
    int e = blockIdx.x * blockDim.x + threadIdx.x;
    if (e < NE) atomicAdd(&d_ecnt[dst[e]], 1);
}

__global__ void k_dinv() {
    int i = blockIdx.x * blockDim.x + threadIdx.x;
    if (i < NN) d_dinv[i] = rsqrtf((float)d_ecnt[i] + 1.0f);  // +1 self loop
}

// ---- 3-stage coalesced exclusive scan of d_ecnt -> d_rowptr ----
__global__ void k_bsum() {   // NB blocks x 256
    __shared__ int s[256];
    int t = threadIdx.x;
    int i = blockIdx.x * 256 + t;
    s[t] = (i < NN) ? d_ecnt[i] : 0;
    __syncthreads();
    #pragma unroll
    for (int off = 128; off > 0; off >>= 1) {
        if (t < off) s[t] += s[t + off];
        __syncthreads();
    }
    if (t == 0) d_bsum[blockIdx.x] = s[0];
}

__global__ void k_bscan() {  // 1 block x 256: exclusive scan of NB block sums
    __shared__ int s[256];
    int t = threadIdx.x;
    int v0 = (t < NB) ? d_bsum[t] : 0;
    s[t] = v0;
    __syncthreads();
    #pragma unroll
    for (int off = 1; off < 256; off <<= 1) {
        int v = (t >= off) ? s[t - off] : 0;
        __syncthreads();
        s[t] += v;
        __syncthreads();
    }
    d_boff[t] = s[t] - v0;   // exclusive
}

__global__ void k_escan() {  // NB blocks x 256: intra-block inclusive + offset
    __shared__ int s[256];
    int t = threadIdx.x;
    int i = blockIdx.x * 256 + t;
    int v0 = (i < NN) ? d_ecnt[i] : 0;
    s[t] = v0;
    __syncthreads();
    #pragma unroll
    for (int off = 1; off < 256; off <<= 1) {
        int v = (t >= off) ? s[t - off] : 0;
        __syncthreads();
        s[t] += v;
        __syncthreads();
    }
    if (i < NN) d_rowptr[i + 1] = d_boff[blockIdx.x] + s[t];
    if (i == 0) d_rowptr[0] = 0;
}

__global__ void k_scatter(const int* __restrict__ src, const int* __restrict__ dst) {
    int e = blockIdx.x * blockDim.x + threadIdx.x;
    if (e >= NE) return;
    int s = src[e], d = dst[e];
    int pos = d_rowptr[d] + atomicAdd(&d_cursor[d], 1);
    d_csr_src[pos] = s;
    d_csr_dst[pos] = d;
    d_csr_norm[pos] = d_dinv[s] * d_dinv[d];
}

// ---------------- x0 = [nodes | cat_emb[cats]]  [NN,64] ----------------
__global__ void k_embed(const float* __restrict__ nodes, const int* __restrict__ cats,
                        const float* __restrict__ emb) {
    int t = blockIdx.x * blockDim.x + threadIdx.x;
    if (t >= NN * 16) return;
    int node = t >> 4, j = t & 15;
    float4 v;
    if (j < 8) v = ((const float4*)nodes)[node * 8 + j];
    else       v = ((const float4*)emb)[(size_t)cats[node] * 8 + (j - 8)];
    ((float4*)d_x0)[node * 16 + j] = v;
}

// ---------------- GEMM: Y[M,128] = X[M,K] @ (W0 - W1)[K,128] (+bias) ----------------
__global__ void __launch_bounds__(512)
gemm_n128(const float* __restrict__ X, int M, int K,
          const float* __restrict__ W0, const float* __restrict__ W1,
          const float* __restrict__ bias,
          float* __restrict__ Y) {
    extern __shared__ float sm[];
    float* sA = sm;              // [64][128]  k-major
    float* sW = sm + 64 * 128;   // [64][128]
    const int t = threadIdx.x;
    const int row0 = blockIdx.x * 128;
    const int tr = (t >> 4) << 2;   // 4 rows
    const int tc = (t & 15) << 3;   // 8 cols (4 packed)
    unsigned long long acc[4][4];
    #pragma unroll
    for (int i = 0; i < 4; i++)
        #pragma unroll
        for (int j = 0; j < 4; j++) acc[i][j] = 0ULL;

    for (int k0 = 0; k0 < K; k0 += 64) {
        #pragma unroll
        for (int i = t; i < 2048; i += 512) {
            int r = i & 127, c4 = i >> 7;
            float4 v = make_float4(0.f, 0.f, 0.f, 0.f);
            int gr = row0 + r;
            if (gr < M) v = *(const float4*)(X + (size_t)gr * K + k0 + (c4 << 2));
            int kk = c4 << 2;
            sA[(kk + 0) * 128 + r] = v.x;
            sA[(kk + 1) * 128 + r] = v.y;
            sA[(kk + 2) * 128 + r] = v.z;
            sA[(kk + 3) * 128 + r] = v.w;
        }
        #pragma unroll
        for (int i = t; i < 2048; i += 512) {
            int r = i >> 5, c4 = i & 31;
            float4 v = *(const float4*)(W0 + (size_t)(k0 + r) * 128 + (c4 << 2));
            if (W1) {
                float4 u = *(const float4*)(W1 + (size_t)(k0 + r) * 128 + (c4 << 2));
                v.x -= u.x; v.y -= u.y; v.z -= u.z; v.w -= u.w;
            }
            *(float4*)(sW + r * 128 + (c4 << 2)) = v;
        }
        __syncthreads();
        #pragma unroll 4
        for (int kk = 0; kk < 64; ++kk) {
            float4 av = *(const float4*)(sA + kk * 128 + tr);
            ulonglong2 w0 = *(const ulonglong2*)(sW + kk * 128 + tc);
            ulonglong2 w1 = *(const ulonglong2*)(sW + kk * 128 + tc + 4);
            unsigned long long a0 = dup2(av.x), a1 = dup2(av.y),
                               a2 = dup2(av.z), a3 = dup2(av.w);
            acc[0][0] = fma2(a0, w0.x, acc[0][0]);
            acc[0][1] = fma2(a0, w0.y, acc[0][1]);
            acc[0][2] = fma2(a0, w1.x, acc[0][2]);
            acc[0][3] = fma2(a0, w1.y, acc[0][3]);
            acc[1][0] = fma2(a1, w0.x, acc[1][0]);
            acc[1][1] = fma2(a1, w0.y, acc[1][1]);
            acc[1][2] = fma2(a1, w1.x, acc[1][2]);
            acc[1][3] = fma2(a1, w1.y, acc[1][3]);
            acc[2][0] = fma2(a2, w0.x, acc[2][0]);
            acc[2][1] = fma2(a2, w0.y, acc[2][1]);
            acc[2][2] = fma2(a2, w1.x, acc[2][2]);
            acc[2][3] = fma2(a2, w1.y, acc[2][3]);
            acc[3][0] = fma2(a3, w0.x, acc[3][0]);
            acc[3][1] = fma2(a3, w0.y, acc[3][1]);
            acc[3][2] = fma2(a3, w1.x, acc[3][2]);
            acc[3][3] = fma2(a3, w1.y, acc[3][3]);
        }
        __syncthreads();
    }
    float bv[8];
    if (bias) {
        *(float4*)(bv)     = *(const float4*)(bias + tc);
        *(float4*)(bv + 4) = *(const float4*)(bias + tc + 4);
    } else {
        #pragma unroll
        for (int j = 0; j < 8; j++) bv[j] = 0.f;
    }
    #pragma unroll
    for (int i = 0; i < 4; i++) {
        int gr = row0 + tr + i;
        if (gr < M) {
            float o[8];
            #pragma unroll
            for (int j = 0; j < 4; j++) {
                float2 f = unpack2(acc[i][j]);
                o[2 * j]     = f.x + bv[2 * j];
                o[2 * j + 1] = f.y + bv[2 * j + 1];
            }
            *(float4*)(Y + (size_t)gr * 128 + tc)     = *(float4*)(o);
            *(float4*)(Y + (size_t)gr * 128 + tc + 4) = *(float4*)(o + 4);
        }
    }
}

// ---------------- GCN aggregation ----------------
__global__ void gcn_agg(const float* __restrict__ H, const float* __restrict__ bias,
                        float* __restrict__ out) {
    int warp = threadIdx.x >> 5;
    int lane = threadIdx.x & 31;
    int node = blockIdx.x * 8 + warp;
    if (node >= NN) return;
    float dv = d_dinv[node];
    float sn = dv * dv;
    float4 acc = ((const float4*)H)[node * 32 + lane];
    acc.x *= sn; acc.y *= sn; acc.z *= sn; acc.w *= sn;
    int beg = d_rowptr[node], end = d_rowptr[node + 1];
    int e = beg;
    for (; e + 1 < end; e += 2) {
        int s0 = d_csr_src[e], s1 = d_csr_src[e + 1];
        float n0 = d_csr_norm[e], n1 = d_csr_norm[e + 1];
        float4 h0 = ((const float4*)H)[s0 * 32 + lane];
        float4 h1 = ((const float4*)H)[s1 * 32 + lane];
        acc.x = fmaf(h0.x, n0, acc.x); acc.y = fmaf(h0.y, n0, acc.y);
        acc.z = fmaf(h0.z, n0, acc.z); acc.w = fmaf(h0.w, n0, acc.w);
        acc.x = fmaf(h1.x, n1, acc.x); acc.y = fmaf(h1.y, n1, acc.y);
        acc.z = fmaf(h1.z, n1, acc.z); acc.w = fmaf(h1.w, n1, acc.w);
    }
    if (e < end) {
        int s = d_csr_src[e];
        float nm = d_csr_norm[e];
        float4 h = ((const float4*)H)[s * 32 + lane];
        acc.x = fmaf(h.x, nm, acc.x); acc.y = fmaf(h.y, nm, acc.y);
        acc.z = fmaf(h.z, nm, acc.z); acc.w = fmaf(h.w, nm, acc.w);
    }
    float4 b = ((const float4*)bias)[lane];
    float4 r;
    r.x = fmaxf(acc.x + b.x, 0.f);
    r.y = fmaxf(acc.y + b.y, 0.f);
    r.z = fmaxf(acc.z + b.z, 0.f);
    r.w = fmaxf(acc.w + b.w, 0.f);
    ((float4*)out)[node * 32 + lane] = r;
}

__global__ void k_zero(float* __restrict__ p, int n4) {
    int i = blockIdx.x * blockDim.x + threadIdx.x;
    if (i < n4) ((float4*)p)[i] = make_float4(0.f, 0.f, 0.f, 0.f);
}

// ---------------- EdgeConv per-edge MLP + segment-max ----------------
// 64 edges/block, 256 threads. We2 read via L1 (__ldg). smem: sT[128][68] reused as sR[64][132].
__global__ void __launch_bounds__(256, 4)
edge_mlp(const float* __restrict__ A, const float* __restrict__ Bm,
         const float* __restrict__ We2, const float* __restrict__ be2,
         float* __restrict__ agg) {
    extern __shared__ float sT[];      // 128*68 floats = 34816 B
    __shared__ int sDst[64];
    __shared__ int sSrc[64];
    const int t = threadIdx.x;
    const int e0 = blockIdx.x * 64;
    if (t < 64) { sDst[t] = d_csr_dst[e0 + t]; sSrc[t] = d_csr_src[e0 + t]; }
    __syncthreads();

    // gather relu(A[dst]+B[src]) into k-major sT[k][e], pad 68
    {
        int e = t & 63;
        int d = sDst[e], s = sSrc[e];
        const float4* Ad = (const float4*)(A  + (size_t)d * 128);
        const float4* Bs = (const float4*)(Bm + (size_t)s * 128);
        #pragma unroll
        for (int c4 = (t >> 6); c4 < 32; c4 += 4) {
            float4 av = __ldg(Ad + c4);
            float4 bv = __ldg(Bs + c4);
            int kk = c4 << 2;
            sT[(kk + 0) * 68 + e] = fmaxf(av.x + bv.x, 0.f);
            sT[(kk + 1) * 68 + e] = fmaxf(av.y + bv.y, 0.f);
            sT[(kk + 2) * 68 + e] = fmaxf(av.z + bv.z, 0.f);
            sT[(kk + 3) * 68 + e] = fmaxf(av.w + bv.w, 0.f);
        }
    }
    __syncthreads();

    const int tr = (t >> 4) << 2;   // 4 edges (0..60)
    const int tc = (t & 15) << 3;   // 8 cols (4 packed)
    unsigned long long acc[4][4];
    #pragma unroll
    for (int i = 0; i < 4; i++)
        #pragma unroll
        for (int j = 0; j < 4; j++) acc[i][j] = 0ULL;
    #pragma unroll 4
    for (int k = 0; k < 128; ++k) {
        float4 av = *(const float4*)(sT + k * 68 + tr);
        ulonglong2 w0 = __ldg((const ulonglong2*)(We2 + (size_t)k * 128 + tc));
        ulonglong2 w1 = __ldg((const ulonglong2*)(We2 + (size_t)k * 128 + tc + 4));
        unsigned long long a0 = dup2(av.x), a1 = dup2(av.y),
                           a2 = dup2(av.z), a3 = dup2(av.w);
        acc[0][0] = fma2(a0, w0.x, acc[0][0]);
        acc[0][1] = fma2(a0, w0.y, acc[0][1]);
        acc[0][2] = fma2(a0, w1.x, acc[0][2]);
        acc[0][3] = fma2(a0, w1.y, acc[0][3]);
        acc[1][0] = fma2(a1, w0.x, acc[1][0]);
        acc[1][1] = fma2(a1, w0.y, acc[1][1]);
        acc[1][2] = fma2(a1, w1.x, acc[1][2]);
        acc[1][3] = fma2(a1, w1.y, acc[1][3]);
        acc[2][0] = fma2(a2, w0.x, acc[2][0]);
        acc[2][1] = fma2(a2, w0.y, acc[2][1]);
        acc[2][2] = fma2(a2, w1.x, acc[2][2]);
        acc[2][3] = fma2(a2, w1.y, acc[2][3]);
        acc[3][0] = fma2(a3, w0.x, acc[3][0]);
        acc[3][1] = fma2(a3, w0.y, acc[3][1]);
        acc[3][2] = fma2(a3, w1.x, acc[3][2]);
        acc[3][3] = fma2(a3, w1.y, acc[3][3]);
    }
    __syncthreads();   // all reads of sT done; reuse as sR[e][132]

    {
        float bv[8];
        *(float4*)(bv)     = __ldg((const float4*)(be2 + tc));
        *(float4*)(bv + 4) = __ldg((const float4*)(be2 + tc + 4));
        #pragma unroll
        for (int i = 0; i < 4; i++) {
            float o[8];
            #pragma unroll
            for (int j = 0; j < 4; j++) {
                float2 f = unpack2(acc[i][j]);
                o[2 * j]     = f.x + bv[2 * j];
                o[2 * j + 1] = f.y + bv[2 * j + 1];
            }
            *(float4*)(sT + (tr + i) * 132 + tc)     = *(float4*)(o);
            *(float4*)(sT + (tr + i) * 132 + tc + 4) = *(float4*)(o + 4);
        }
    }
    __syncthreads();

    // per-(col, quarter) dst-run reduction -> one atomicMax per run
    {
        int col = t >> 1;         // 0..127
        int q = t & 1;            // half of 64 edges
        int eb = q * 32;
        int cur = sDst[eb];
        float m = sT[eb * 132 + col];
        #pragma unroll 4
        for (int i = 1; i < 32; ++i) {
            int e = eb + i;
            int d = sDst[e];
            float v = sT[e * 132 + col];
            if (d != cur) {
                if (m > 0.f) atomicMax((int*)(agg + (size_t)cur * 128 + col), __float_as_int(m));
                cur = d; m = v;
            } else {
                m = fmaxf(m, v);
            }
        }
        if (m > 0.f) atomicMax((int*)(agg + (size_t)cur * 128 + col), __float_as_int(m));
    }
}

// ---------------- pooling ----------------
__global__ void k_zero_pool() {
    int i = blockIdx.x * blockDim.x + threadIdx.x;
    if (i < NG * 128) { d_gmax[i] = 0.f; d_gsum[i] = 0.f; }
    if (i < NG) d_gcnt[i] = 0.f;
}

// block handles 128 contiguous nodes (batch sorted): run-accumulate, flush per run
__global__ void __launch_bounds__(256)
k_pool2(const int* __restrict__ batch, const float* __restrict__ X) {
    int base = blockIdx.x * 128;
    int ch = threadIdx.x & 127;
    int half = threadIdx.x >> 7;
    int cur = -1;
    float vmax = 0.f, vsum = 0.f;
    for (int i = half; i < 128; i += 2) {
        int n = base + i;
        if (n >= NN) break;
        int g = batch[n];
        if (g != cur) {
            if (cur >= 0) {
                atomicAdd(&d_gsum[cur * 128 + ch], vsum);
                if (vmax > 0.f) atomicMax((int*)&d_gmax[cur * 128 + ch], __float_as_int(vmax));
            }
            cur = g; vmax = 0.f; vsum = 0.f;
        }
        float v = X[(size_t)n * 128 + ch];
        vsum += v;
        vmax = fmaxf(vmax, v);
    }
    if (cur >= 0) {
        atomicAdd(&d_gsum[cur * 128 + ch], vsum);
        if (vmax > 0.f) atomicMax((int*)&d_gmax[cur * 128 + ch], __float_as_int(vmax));
    }
    if (threadIdx.x == 0) {   // counts
        int c = -1; float cnt = 0.f;
        for (int i = 0; i < 128; ++i) {
            int n = base + i;
            if (n >= NN) break;
            int g = batch[n];
            if (g != c) {
                if (c >= 0) atomicAdd(&d_gcnt[c], cnt);
                c = g; cnt = 0.f;
            }
            cnt += 1.f;
        }
        if (c >= 0) atomicAdd(&d_gcnt[c], cnt);
    }
}

__global__ void k_pool_fin() {
    int t = blockIdx.x * blockDim.x + threadIdx.x;
    if (t >= NG * 256) return;
    int g = t >> 8, c = t & 255;
    float v;
    if (c < 128) v = d_gmax[g * 128 + c];
    else         v = d_gsum[g * 128 + c - 128] / fmaxf(d_gcnt[g], 1.0f);
    d_g[t] = v;
}

// ---------------- head: out = relu(in[64,256] @ W[256,256] + b) ----------------
__global__ void head_gemm(const float* __restrict__ in, const float* __restrict__ W,
                          const float* __restrict__ b, float* __restrict__ out) {
    __shared__ float srow[256];
    int t = threadIdx.x;
    int g = blockIdx.x;
    srow[t] = in[g * 256 + t];
    __syncthreads();
    float acc = b[t];
    #pragma unroll 8
    for (int k = 0; k < 256; ++k) acc = fmaf(srow[k], W[k * 256 + t], acc);
    out[g * 256 + t] = fmaxf(acc, 0.f);
}

// ---------------- launch ----------------
extern "C" void kernel_launch(void* const* d_in, const int* in_sizes, int n_in,
                              void* d_out, int out_size) {
    const float* nodes   = (const float*)d_in[0];
    const int*   cats    = (const int*)d_in[1];
    const int*   ei      = (const int*)d_in[2];
    const int*   batch   = (const int*)d_in[3];
    const float* cat_emb = (const float*)d_in[4];
    const float* W1  = (const float*)d_in[5];
    const float* b1  = (const float*)d_in[6];
    const float* W2  = (const float*)d_in[7];
    const float* b2  = (const float*)d_in[8];
    const float* W3  = (const float*)d_in[9];
    const float* b3  = (const float*)d_in[10];
    const float* We1 = (const float*)d_in[11];
    const float* be1 = (const float*)d_in[12];
    const float* We2 = (const float*)d_in[13];
    const float* be2 = (const float*)d_in[14];
    const float* Wf1 = (const float*)d_in[15];
    const float* bf1 = (const float*)d_in[16];
    const float* Wf2 = (const float*)d_in[17];
    const float* bf2 = (const float*)d_in[18];
    const int* src = ei;
    const int* dst = ei + NE;
    float* out = (float*)d_out;

    cudaFuncSetAttribute(gemm_n128, cudaFuncAttributeMaxDynamicSharedMemorySize, 65536);
    cudaFuncSetAttribute(edge_mlp,  cudaFuncAttributeMaxDynamicSharedMemorySize, 34816);

    float *bufA, *bufB, *bufC, *x0, *g, *h1;
    cudaGetSymbolAddress((void**)&bufA, d_bufA);
    cudaGetSymbolAddress((void**)&bufB, d_bufB);
    cudaGetSymbolAddress((void**)&bufC, d_bufC);
    cudaGetSymbolAddress((void**)&x0,   d_x0);
    cudaGetSymbolAddress((void**)&g,    d_g);
    cudaGetSymbolAddress((void**)&h1,   d_h1);

    // CSR + norms
    k_init<<<(NN + 255) / 256, 256>>>();
    k_count<<<(NE + 255) / 256, 256>>>(dst);
    k_dinv<<<(NN + 255) / 256, 256>>>();
    k_bsum<<<NB, 256>>>();
    k_bscan<<<1, 256>>>();
    k_escan<<<NB, 256>>>();
    k_scatter<<<(NE + 255) / 256, 256>>>(src, dst);

    // x0 = [nodes | emb]
    k_embed<<<(NN * 16 + 255) / 256, 256>>>(nodes, cats, cat_emb);

    const int gg = (NN + 127) / 128;  // 391
    // GCN 1
    gemm_n128<<<gg, 512, 65536>>>(x0, NN, 64, W1, nullptr, nullptr, bufA);
    gcn_agg<<<(NN + 7) / 8, 256>>>(bufA, b1, bufB);
    // GCN 2
    gemm_n128<<<gg, 512, 65536>>>(bufB, NN, 128, W2, nullptr, nullptr, bufA);
    gcn_agg<<<(NN + 7) / 8, 256>>>(bufA, b2, bufB);
    // GCN 3
    gemm_n128<<<gg, 512, 65536>>>(bufB, NN, 128, W3, nullptr, nullptr, bufA);
    gcn_agg<<<(NN + 7) / 8, 256>>>(bufA, b3, bufC);   // x3 -> bufC

    // EdgeConv precompute: A = x3 @ (We1_top - We1_bot) + be1 ; B = x3 @ We1_bot
    gemm_n128<<<gg, 512, 65536>>>(bufC, NN, 128, We1, We1 + 128 * 128, be1, bufA);
    gemm_n128<<<gg, 512, 65536>>>(bufC, NN, 128, We1 + 128 * 128, nullptr, nullptr, bufB);

    // EdgeConv per-edge MLP + segment max (into bufC, init 0; final relu implicit)
    k_zero<<<(NN * 32 + 255) / 256, 256>>>(bufC, NN * 32);
    edge_mlp<<<NE / 64, 256, 34816>>>(bufA, bufB, We2, be2, bufC);

    // pooling
    k_zero_pool<<<(NG * 128 + 255) / 256, 256>>>();
    k_pool2<<<(NN + 127) / 128, 256>>>(batch, bufC);
    k_pool_fin<<<(NG * 256 + 255) / 256, 256>>>();

    // head
    head_gemm<<<NG, 256>>>(g, Wf1, bf1, h1);
    head_gemm<<<NG, 256>>>(h1, Wf2, bf2, out);
}

// round 4
// speedup vs baseline: 1.7575x; 1.1916x over previous
#include <cuda_runtime.h>
#include <cstddef>

#define NN 50000
#define NE 800000
#define NG 64
#define NB 196   // ceil(NN/256)

// ---------------- scratch (__device__ globals; no allocation allowed) ----------------
__device__ __align__(16) float d_x0[NN * 64];
__device__ __align__(16) float d_bufA[NN * 128];
__device__ __align__(16) float d_bufB[NN * 128];
__device__ __align__(16) float d_bufC[NN * 128];
__device__ __align__(16) float d_dinv[NN];
__device__ int d_ecnt[NN];
__device__ int d_cursor[NN];
__device__ int d_rowptr[NN + 1];
__device__ int d_bsum[256];
__device__ int d_boff[256];
__device__ int d_csr_src[NE];
__device__ int d_csr_dst[NE];
__device__ __align__(16) float d_csr_norm[NE];
__device__ __align__(16) float d_gmax[NG * 128];
__device__ __align__(16) float d_gsum[NG * 128];
__device__ float d_gcnt[NG];
__device__ __align__(16) float d_g[NG * 256];
__device__ __align__(16) float d_h1[NG * 256];

// ---------------- packed f32x2 helpers ----------------
__device__ __forceinline__ unsigned long long fma2(unsigned long long a,
                                                   unsigned long long b,
                                                   unsigned long long c) {
    unsigned long long d;
    asm("fma.rn.f32x2 %0, %1, %2, %3;" : "=l"(d) : "l"(a), "l"(b), "l"(c));
    return d;
}
__device__ __forceinline__ unsigned long long dup2(float x) {
    unsigned long long d;
    asm("mov.b64 %0, {%1, %1};" : "=l"(d) : "f"(x));
    return d;
}
__device__ __forceinline__ float2 unpack2(unsigned long long v) {
    float2 r;
    asm("mov.b64 {%0, %1}, %2;" : "=f"(r.x), "=f"(r.y) : "l"(v));
    return r;
}

// ---------------- graph preprocessing ----------------
__global__ void k_init() {
    int i = blockIdx.x * blockDim.x + threadIdx.x;
    if (i < NN) { d_ecnt[i] = 0; d_cursor[i] = 0; }
}

__global__ void k_count(const int* __restrict__ dst) {
    int e = blockIdx.x * blockDim.x + threadIdx.x;
    if (e < NE) atomicAdd(&d_ecnt[dst[e]], 1);
}

__global__ void k_dinv() {
    int i = blockIdx.x * blockDim.x + threadIdx.x;
    if (i < NN) d_dinv[i] = rsqrtf((float)d_ecnt[i] + 1.0f);  // +1 self loop
}

// ---- 3-stage coalesced exclusive scan of d_ecnt -> d_rowptr ----
__global__ void k_bsum() {
    __shared__ int s[256];
    int t = threadIdx.x;
    int i = blockIdx.x * 256 + t;
    s[t] = (i < NN) ? d_ecnt[i] : 0;
    __syncthreads();
    #pragma unroll
    for (int off = 128; off > 0; off >>= 1) {
        if (t < off) s[t] += s[t + off];
        __syncthreads();
    }
    if (t == 0) d_bsum[blockIdx.x] = s[0];
}

__global__ void k_bscan() {
    __shared__ int s[256];
    int t = threadIdx.x;
    int v0 = (t < NB) ? d_bsum[t] : 0;
    s[t] = v0;
    __syncthreads();
    #pragma unroll
    for (int off = 1; off < 256; off <<= 1) {
        int v = (t >= off) ? s[t - off] : 0;
        __syncthreads();
        s[t] += v;
        __syncthreads();
    }
    d_boff[t] = s[t] - v0;
}

__global__ void k_escan() {
    __shared__ int s[256];
    int t = threadIdx.x;
    int i = blockIdx.x * 256 + t;
    int v0 = (i < NN) ? d_ecnt[i] : 0;
    s[t] = v0;
    __syncthreads();
    #pragma unroll
    for (int off = 1; off < 256; off <<= 1) {
        int v = (t >= off) ? s[t - off] : 0;
        __syncthreads();
        s[t] += v;
        __syncthreads();
    }
    if (i < NN) d_rowptr[i + 1] = d_boff[blockIdx.x] + s[t];
    if (i == 0) d_rowptr[0] = 0;
}

__global__ void k_scatter(const int* __restrict__ src, const int* __restrict__ dst) {
    int e = blockIdx.x * blockDim.x + threadIdx.x;
    if (e >= NE) return;
    int s = src[e], d = dst[e];
    int pos = d_rowptr[d] + atomicAdd(&d_cursor[d], 1);
    d_csr_src[pos] = s;
    d_csr_dst[pos] = d;
    d_csr_norm[pos] = d_dinv[s] * d_dinv[d];
}

// ---------------- x0 = [nodes | cat_emb[cats]]  [NN,64] ----------------
__global__ void k_embed(const float* __restrict__ nodes, const int* __restrict__ cats,
                        const float* __restrict__ emb) {
    int t = blockIdx.x * blockDim.x + threadIdx.x;
    if (t >= NN * 16) return;
    int node = t >> 4, j = t & 15;
    float4 v;
    if (j < 8) v = ((const float4*)nodes)[node * 8 + j];
    else       v = ((const float4*)emb)[(size_t)cats[node] * 8 + (j - 8)];
    ((float4*)d_x0)[node * 16 + j] = v;
}

// ---------------- GEMM: Y[M,128] = X[M,K] @ (W0 - W1)[K,128] (+bias) ----------------
__global__ void __launch_bounds__(512)
gemm_n128(const float* __restrict__ X, int M, int K,
          const float* __restrict__ W0, const float* __restrict__ W1,
          const float* __restrict__ bias,
          float* __restrict__ Y) {
    extern __shared__ float sm[];
    float* sA = sm;              // [64][128]  k-major
    float* sW = sm + 64 * 128;   // [64][128]
    const int t = threadIdx.x;
    const int row0 = blockIdx.x * 128;
    const int tr = (t >> 4) << 2;
    const int tc = (t & 15) << 3;
    unsigned long long acc[4][4];
    #pragma unroll
    for (int i = 0; i < 4; i++)
        #pragma unroll
        for (int j = 0; j < 4; j++) acc[i][j] = 0ULL;

    for (int k0 = 0; k0 < K; k0 += 64) {
        #pragma unroll
        for (int i = t; i < 2048; i += 512) {
            int r = i & 127, c4 = i >> 7;
            float4 v = make_float4(0.f, 0.f, 0.f, 0.f);
            int gr = row0 + r;
            if (gr < M) v = *(const float4*)(X + (size_t)gr * K + k0 + (c4 << 2));
            int kk = c4 << 2;
            sA[(kk + 0) * 128 + r] = v.x;
            sA[(kk + 1) * 128 + r] = v.y;
            sA[(kk + 2) * 128 + r] = v.z;
            sA[(kk + 3) * 128 + r] = v.w;
        }
        #pragma unroll
        for (int i = t; i < 2048; i += 512) {
            int r = i >> 5, c4 = i & 31;
            float4 v = *(const float4*)(W0 + (size_t)(k0 + r) * 128 + (c4 << 2));
            if (W1) {
                float4 u = *(const float4*)(W1 + (size_t)(k0 + r) * 128 + (c4 << 2));
                v.x -= u.x; v.y -= u.y; v.z -= u.z; v.w -= u.w;
            }
            *(float4*)(sW + r * 128 + (c4 << 2)) = v;
        }
        __syncthreads();
        #pragma unroll 4
        for (int kk = 0; kk < 64; ++kk) {
            float4 av = *(const float4*)(sA + kk * 128 + tr);
            ulonglong2 w0 = *(const ulonglong2*)(sW + kk * 128 + tc);
            ulonglong2 w1 = *(const ulonglong2*)(sW + kk * 128 + tc + 4);
            unsigned long long a0 = dup2(av.x), a1 = dup2(av.y),
                               a2 = dup2(av.z), a3 = dup2(av.w);
            acc[0][0] = fma2(a0, w0.x, acc[0][0]);
            acc[0][1] = fma2(a0, w0.y, acc[0][1]);
            acc[0][2] = fma2(a0, w1.x, acc[0][2]);
            acc[0][3] = fma2(a0, w1.y, acc[0][3]);
            acc[1][0] = fma2(a1, w0.x, acc[1][0]);
            acc[1][1] = fma2(a1, w0.y, acc[1][1]);
            acc[1][2] = fma2(a1, w1.x, acc[1][2]);
            acc[1][3] = fma2(a1, w1.y, acc[1][3]);
            acc[2][0] = fma2(a2, w0.x, acc[2][0]);
            acc[2][1] = fma2(a2, w0.y, acc[2][1]);
            acc[2][2] = fma2(a2, w1.x, acc[2][2]);
            acc[2][3] = fma2(a2, w1.y, acc[2][3]);
            acc[3][0] = fma2(a3, w0.x, acc[3][0]);
            acc[3][1] = fma2(a3, w0.y, acc[3][1]);
            acc[3][2] = fma2(a3, w1.x, acc[3][2]);
            acc[3][3] = fma2(a3, w1.y, acc[3][3]);
        }
        __syncthreads();
    }
    float bv[8];
    if (bias) {
        *(float4*)(bv)     = *(const float4*)(bias + tc);
        *(float4*)(bv + 4) = *(const float4*)(bias + tc + 4);
    } else {
        #pragma unroll
        for (int j = 0; j < 8; j++) bv[j] = 0.f;
    }
    #pragma unroll
    for (int i = 0; i < 4; i++) {
        int gr = row0 + tr + i;
        if (gr < M) {
            float o[8];
            #pragma unroll
            for (int j = 0; j < 4; j++) {
                float2 f = unpack2(acc[i][j]);
                o[2 * j]     = f.x + bv[2 * j];
                o[2 * j + 1] = f.y + bv[2 * j + 1];
            }
            *(float4*)(Y + (size_t)gr * 128 + tc)     = *(float4*)(o);
            *(float4*)(Y + (size_t)gr * 128 + tc + 4) = *(float4*)(o + 4);
        }
    }
}

// ---------------- GCN aggregation ----------------
__global__ void gcn_agg(const float* __restrict__ H, const float* __restrict__ bias,
                        float* __restrict__ out) {
    int warp = threadIdx.x >> 5;
    int lane = threadIdx.x & 31;
    int node = blockIdx.x * 8 + warp;
    if (node >= NN) return;
    float dv = d_dinv[node];
    float sn = dv * dv;
    float4 acc = ((const float4*)H)[node * 32 + lane];
    acc.x *= sn; acc.y *= sn; acc.z *= sn; acc.w *= sn;
    int beg = d_rowptr[node], end = d_rowptr[node + 1];
    int e = beg;
    for (; e + 1 < end; e += 2) {
        int s0 = d_csr_src[e], s1 = d_csr_src[e + 1];
        float n0 = d_csr_norm[e], n1 = d_csr_norm[e + 1];
        float4 h0 = ((const float4*)H)[s0 * 32 + lane];
        float4 h1 = ((const float4*)H)[s1 * 32 + lane];
        acc.x = fmaf(h0.x, n0, acc.x); acc.y = fmaf(h0.y, n0, acc.y);
        acc.z = fmaf(h0.z, n0, acc.z); acc.w = fmaf(h0.w, n0, acc.w);
        acc.x = fmaf(h1.x, n1, acc.x); acc.y = fmaf(h1.y, n1, acc.y);
        acc.z = fmaf(h1.z, n1, acc.z); acc.w = fmaf(h1.w, n1, acc.w);
    }
    if (e < end) {
        int s = d_csr_src[e];
        float nm = d_csr_norm[e];
        float4 h = ((const float4*)H)[s * 32 + lane];
        acc.x = fmaf(h.x, nm, acc.x); acc.y = fmaf(h.y, nm, acc.y);
        acc.z = fmaf(h.z, nm, acc.z); acc.w = fmaf(h.w, nm, acc.w);
    }
    float4 b = ((const float4*)bias)[lane];
    float4 r;
    r.x = fmaxf(acc.x + b.x, 0.f);
    r.y = fmaxf(acc.y + b.y, 0.f);
    r.z = fmaxf(acc.z + b.z, 0.f);
    r.w = fmaxf(acc.w + b.w, 0.f);
    ((float4*)out)[node * 32 + lane] = r;
}

__global__ void k_zero(float* __restrict__ p, int n4) {
    int i = blockIdx.x * blockDim.x + threadIdx.x;
    if (i < n4) ((float4*)p)[i] = make_float4(0.f, 0.f, 0.f, 0.f);
}

// ---------------- EdgeConv per-edge MLP + segment-max ----------------
// 128 edges/block, 256 threads, 8 edges x 8 cols per thread. We2 via __ldg.
// smem sT[128][132] (67.6KB), reused for results.
__global__ void __launch_bounds__(256, 2)
edge_mlp(const float* __restrict__ A, const float* __restrict__ Bm,
         const float* __restrict__ We2, const float* __restrict__ be2,
         float* __restrict__ agg) {
    extern __shared__ float sT[];      // 128*132 floats
    __shared__ int sDst[128];
    __shared__ int sSrc[128];
    const int t = threadIdx.x;
    const int e0 = blockIdx.x * 128;
    if (t < 128) { sDst[t] = d_csr_dst[e0 + t]; sSrc[t] = d_csr_src[e0 + t]; }
    __syncthreads();

    // gather relu(A[dst]+B[src]) into k-major sT[k][e], row stride 132
    {
        int e = t & 127;
        int d = sDst[e], s = sSrc[e];
        const float4* Ad = (const float4*)(A  + (size_t)d * 128);
        const float4* Bs = (const float4*)(Bm + (size_t)s * 128);
        #pragma unroll
        for (int c4 = (t >> 7); c4 < 32; c4 += 2) {
            float4 av = __ldg(Ad + c4);
            float4 bv = __ldg(Bs + c4);
            int kk = c4 << 2;
            sT[(kk + 0) * 132 + e] = fmaxf(av.x + bv.x, 0.f);
            sT[(kk + 1) * 132 + e] = fmaxf(av.y + bv.y, 0.f);
            sT[(kk + 2) * 132 + e] = fmaxf(av.z + bv.z, 0.f);
            sT[(kk + 3) * 132 + e] = fmaxf(av.w + bv.w, 0.f);
        }
    }
    __syncthreads();

    const int tr = (t >> 4) << 3;   // 8 edges
    const int tc = (t & 15) << 3;   // 8 cols (4 packed)
    unsigned long long acc[8][4];
    #pragma unroll
    for (int i = 0; i < 8; i++)
        #pragma unroll
        for (int j = 0; j < 4; j++) acc[i][j] = 0ULL;

    #pragma unroll 2
    for (int k = 0; k < 128; ++k) {
        ulonglong2 w0 = __ldg((const ulonglong2*)(We2 + (size_t)k * 128 + tc));
        ulonglong2 w1 = __ldg((const ulonglong2*)(We2 + (size_t)k * 128 + tc + 4));
        float4 av0 = *(const float4*)(sT + k * 132 + tr);
        float4 av1 = *(const float4*)(sT + k * 132 + tr + 4);
        unsigned long long a;
        a = dup2(av0.x);
        acc[0][0] = fma2(a, w0.x, acc[0][0]); acc[0][1] = fma2(a, w0.y, acc[0][1]);
        acc[0][2] = fma2(a, w1.x, acc[0][2]); acc[0][3] = fma2(a, w1.y, acc[0][3]);
        a = dup2(av0.y);
        acc[1][0] = fma2(a, w0.x, acc[1][0]); acc[1][1] = fma2(a, w0.y, acc[1][1]);
        acc[1][2] = fma2(a, w1.x, acc[1][2]); acc[1][3] = fma2(a, w1.y, acc[1][3]);
        a = dup2(av0.z);
        acc[2][0] = fma2(a, w0.x, acc[2][0]); acc[2][1] = fma2(a, w0.y, acc[2][1]);
        acc[2][2] = fma2(a, w1.x, acc[2][2]); acc[2][3] = fma2(a, w1.y, acc[2][3]);
        a = dup2(av0.w);
        acc[3][0] = fma2(a, w0.x, acc[3][0]); acc[3][1] = fma2(a, w0.y, acc[3][1]);
        acc[3][2] = fma2(a, w1.x, acc[3][2]); acc[3][3] = fma2(a, w1.y, acc[3][3]);
        a = dup2(av1.x);
        acc[4][0] = fma2(a, w0.x, acc[4][0]); acc[4][1] = fma2(a, w0.y, acc[4][1]);
        acc[4][2] = fma2(a, w1.x, acc[4][2]); acc[4][3] = fma2(a, w1.y, acc[4][3]);
        a = dup2(av1.y);
        acc[5][0] = fma2(a, w0.x, acc[5][0]); acc[5][1] = fma2(a, w0.y, acc[5][1]);
        acc[5][2] = fma2(a, w1.x, acc[5][2]); acc[5][3] = fma2(a, w1.y, acc[5][3]);
        a = dup2(av1.z);
        acc[6][0] = fma2(a, w0.x, acc[6][0]); acc[6][1] = fma2(a, w0.y, acc[6][1]);
        acc[6][2] = fma2(a, w1.x, acc[6][2]); acc[6][3] = fma2(a, w1.y, acc[6][3]);
        a = dup2(av1.w);
        acc[7][0] = fma2(a, w0.x, acc[7][0]); acc[7][1] = fma2(a, w0.y, acc[7][1]);
        acc[7][2] = fma2(a, w1.x, acc[7][2]); acc[7][3] = fma2(a, w1.y, acc[7][3]);
    }
    __syncthreads();   // all reads of sT done; reuse as sR[e][132]

    {
        float bv[8];
        *(float4*)(bv)     = __ldg((const float4*)(be2 + tc));
        *(float4*)(bv + 4) = __ldg((const float4*)(be2 + tc + 4));
        #pragma unroll
        for (int i = 0; i < 8; i++) {
            float o[8];
            #pragma unroll
            for (int j = 0; j < 4; j++) {
                float2 f = unpack2(acc[i][j]);
                o[2 * j]     = f.x + bv[2 * j];
                o[2 * j + 1] = f.y + bv[2 * j + 1];
            }
            *(float4*)(sT + (tr + i) * 132 + tc)     = *(float4*)(o);
            *(float4*)(sT + (tr + i) * 132 + tc + 4) = *(float4*)(o + 4);
        }
    }
    __syncthreads();

    // per-(col, half) dst-run reduction -> one atomicMax per run
    {
        int col = t >> 1;         // 0..127
        int q = t & 1;            // half of 128 edges
        int eb = q * 64;
        int cur = sDst[eb];
        float m = sT[eb * 132 + col];
        #pragma unroll 4
        for (int i = 1; i < 64; ++i) {
            int e = eb + i;
            int d = sDst[e];
            float v = sT[e * 132 + col];
            if (d != cur) {
                if (m > 0.f) atomicMax((int*)(agg + (size_t)cur * 128 + col), __float_as_int(m));
                cur = d; m = v;
            } else {
                m = fmaxf(m, v);
            }
        }
        if (m > 0.f) atomicMax((int*)(agg + (size_t)cur * 128 + col), __float_as_int(m));
    }
}

// ---------------- pooling ----------------
__global__ void k_zero_pool() {
    int i = blockIdx.x * blockDim.x + threadIdx.x;
    if (i < NG * 128) { d_gmax[i] = 0.f; d_gsum[i] = 0.f; }
    if (i < NG) d_gcnt[i] = 0.f;
}

__global__ void __launch_bounds__(256)
k_pool2(const int* __restrict__ batch, const float* __restrict__ X) {
    int base = blockIdx.x * 128;
    int ch = threadIdx.x & 127;
    int half = threadIdx.x >> 7;
    int cur = -1;
    float vmax = 0.f, vsum = 0.f;
    for (int i = half; i < 128; i += 2) {
        int n = base + i;
        if (n >= NN) break;
        int g = batch[n];
        if (g != cur) {
            if (cur >= 0) {
                atomicAdd(&d_gsum[cur * 128 + ch], vsum);
                if (vmax > 0.f) atomicMax((int*)&d_gmax[cur * 128 + ch], __float_as_int(vmax));
            }
            cur = g; vmax = 0.f; vsum = 0.f;
        }
        float v = X[(size_t)n * 128 + ch];
        vsum += v;
        vmax = fmaxf(vmax, v);
    }
    if (cur >= 0) {
        atomicAdd(&d_gsum[cur * 128 + ch], vsum);
        if (vmax > 0.f) atomicMax((int*)&d_gmax[cur * 128 + ch], __float_as_int(vmax));
    }
    if (threadIdx.x == 0) {
        int c = -1; float cnt = 0.f;
        for (int i = 0; i < 128; ++i) {
            int n = base + i;
            if (n >= NN) break;
            int g = batch[n];
            if (g != c) {
                if (c >= 0) atomicAdd(&d_gcnt[c], cnt);
                c = g; cnt = 0.f;
            }
            cnt += 1.f;
        }
        if (c >= 0) atomicAdd(&d_gcnt[c], cnt);
    }
}

__global__ void k_pool_fin() {
    int t = blockIdx.x * blockDim.x + threadIdx.x;
    if (t >= NG * 256) return;
    int g = t >> 8, c = t & 255;
    float v;
    if (c < 128) v = d_gmax[g * 128 + c];
    else         v = d_gsum[g * 128 + c - 128] / fmaxf(d_gcnt[g], 1.0f);
    d_g[t] = v;
}

// ---------------- head ----------------
__global__ void head_gemm(const float* __restrict__ in, const float* __restrict__ W,
                          const float* __restrict__ b, float* __restrict__ out) {
    __shared__ float srow[256];
    int t = threadIdx.x;
    int g = blockIdx.x;
    srow[t] = in[g * 256 + t];
    __syncthreads();
    float acc = b[t];
    #pragma unroll 8
    for (int k = 0; k < 256; ++k) acc = fmaf(srow[k], W[k * 256 + t], acc);
    out[g * 256 + t] = fmaxf(acc, 0.f);
}

// ---------------- launch ----------------
extern "C" void kernel_launch(void* const* d_in, const int* in_sizes, int n_in,
                              void* d_out, int out_size) {
    const float* nodes   = (const float*)d_in[0];
    const int*   cats    = (const int*)d_in[1];
    const int*   ei      = (const int*)d_in[2];
    const int*   batch   = (const int*)d_in[3];
    const float* cat_emb = (const float*)d_in[4];
    const float* W1  = (const float*)d_in[5];
    const float* b1  = (const float*)d_in[6];
    const float* W2  = (const float*)d_in[7];
    const float* b2  = (const float*)d_in[8];
    const float* W3  = (const float*)d_in[9];
    const float* b3  = (const float*)d_in[10];
    const float* We1 = (const float*)d_in[11];
    const float* be1 = (const float*)d_in[12];
    const float* We2 = (const float*)d_in[13];
    const float* be2 = (const float*)d_in[14];
    const float* Wf1 = (const float*)d_in[15];
    const float* bf1 = (const float*)d_in[16];
    const float* Wf2 = (const float*)d_in[17];
    const float* bf2 = (const float*)d_in[18];
    const int* src = ei;
    const int* dst = ei + NE;
    float* out = (float*)d_out;

    cudaFuncSetAttribute(gemm_n128, cudaFuncAttributeMaxDynamicSharedMemorySize, 65536);
    cudaFuncSetAttribute(edge_mlp,  cudaFuncAttributeMaxDynamicSharedMemorySize, 128 * 132 * 4);

    float *bufA, *bufB, *bufC, *x0, *g, *h1;
    cudaGetSymbolAddress((void**)&bufA, d_bufA);
    cudaGetSymbolAddress((void**)&bufB, d_bufB);
    cudaGetSymbolAddress((void**)&bufC, d_bufC);
    cudaGetSymbolAddress((void**)&x0,   d_x0);
    cudaGetSymbolAddress((void**)&g,    d_g);
    cudaGetSymbolAddress((void**)&h1,   d_h1);

    // CSR + norms
    k_init<<<(NN + 255) / 256, 256>>>();
    k_count<<<(NE + 255) / 256, 256>>>(dst);
    k_dinv<<<(NN + 255) / 256, 256>>>();
    k_bsum<<<NB, 256>>>();
    k_bscan<<<1, 256>>>();
    k_escan<<<NB, 256>>>();
    k_scatter<<<(NE + 255) / 256, 256>>>(src, dst);

    // x0 = [nodes | emb]
    k_embed<<<(NN * 16 + 255) / 256, 256>>>(nodes, cats, cat_emb);

    const int gg = (NN + 127) / 128;  // 391
    // GCN 1
    gemm_n128<<<gg, 512, 65536>>>(x0, NN, 64, W1, nullptr, nullptr, bufA);
    gcn_agg<<<(NN + 7) / 8, 256>>>(bufA, b1, bufB);
    // GCN 2
    gemm_n128<<<gg, 512, 65536>>>(bufB, NN, 128, W2, nullptr, nullptr, bufA);
    gcn_agg<<<(NN + 7) / 8, 256>>>(bufA, b2, bufB);
    // GCN 3
    gemm_n128<<<gg, 512, 65536>>>(bufB, NN, 128, W3, nullptr, nullptr, bufA);
    gcn_agg<<<(NN + 7) / 8, 256>>>(bufA, b3, bufC);   // x3 -> bufC

    // EdgeConv precompute: A = x3 @ (We1_top - We1_bot) + be1 ; B = x3 @ We1_bot
    gemm_n128<<<gg, 512, 65536>>>(bufC, NN, 128, We1, We1 + 128 * 128, be1, bufA);
    gemm_n128<<<gg, 512, 65536>>>(bufC, NN, 128, We1 + 128 * 128, nullptr, nullptr, bufB);

    // EdgeConv per-edge MLP + segment max
    k_zero<<<(NN * 32 + 255) / 256, 256>>>(bufC, NN * 32);
    edge_mlp<<<NE / 128, 256, 128 * 132 * 4>>>(bufA, bufB, We2, be2, bufC);

    // pooling
    k_zero_pool<<<(NG * 128 + 255) / 256, 256>>>();
    k_pool2<<<(NN + 127) / 128, 256>>>(batch, bufC);
    k_pool_fin<<<(NG * 256 + 255) / 256, 256>>>();

    // head
    head_gemm<<<NG, 256>>>(g, Wf1, bf1, h1);
    head_gemm<<<NG, 256>>>(h1, Wf2, bf2, out);
}

// round 6
// speedup vs baseline: 2.1174x; 1.2048x over previous
#include <cuda_runtime.h>
#include <cuda_bf16.h>
#include <cstddef>
#include <cstdint>

#define NN 50000
#define NE 800000
#define NG 64
#define NB 196   // ceil(NN/256)

// ---------------- scratch (__device__ globals; no allocation allowed) ----------------
__device__ __align__(16) float d_x0[NN * 64];
__device__ __align__(16) float d_bufA[NN * 128];
__device__ __align__(16) float d_bufB[NN * 128];
__device__ __align__(16) float d_bufC[NN * 128];
__device__ __align__(16) float d_dinv[NN];
__device__ int d_ecnt[NN];
__device__ int d_cursor[NN];
__device__ int d_rowptr[NN + 1];
__device__ int d_bsum[256];
__device__ int d_boff[256];
__device__ int d_csr_src[NE];
__device__ int d_csr_dst[NE];
__device__ __align__(16) float d_csr_norm[NE];
__device__ __align__(16) float d_gmax[NG * 128];
__device__ __align__(16) float d_gsum[NG * 128];
__device__ float d_gcnt[NG];
__device__ __align__(16) float d_g[NG * 256];
__device__ __align__(16) float d_h1[NG * 256];
// prebuilt We2^T bf16 hi/lo images: [n][k] rows, stride 136 elems (272 B, 16B-aligned rows)
__device__ __align__(16) __nv_bfloat16 d_Whi[128 * 136];
__device__ __align__(16) __nv_bfloat16 d_Wlo[128 * 136];

// ---------------- packed f32x2 helpers ----------------
__device__ __forceinline__ unsigned long long fma2(unsigned long long a,
                                                   unsigned long long b,
                                                   unsigned long long c) {
    unsigned long long d;
    asm("fma.rn.f32x2 %0, %1, %2, %3;" : "=l"(d) : "l"(a), "l"(b), "l"(c));
    return d;
}
__device__ __forceinline__ unsigned long long dup2(float x) {
    unsigned long long d;
    asm("mov.b64 %0, {%1, %1};" : "=l"(d) : "f"(x));
    return d;
}
__device__ __forceinline__ float2 unpack2(unsigned long long v) {
    float2 r;
    asm("mov.b64 {%0, %1}, %2;" : "=f"(r.x), "=f"(r.y) : "l"(v));
    return r;
}

// ---------------- mma.sync helpers ----------------
__device__ __forceinline__ uint32_t smem_u32(const void* p) {
    uint32_t a;
    asm("{ .reg .u64 t; cvta.to.shared.u64 t, %1; cvt.u32.u64 %0, t; }" : "=r"(a) : "l"(p));
    return a;
}
__device__ __forceinline__ void ldm_x4(uint32_t* r, uint32_t addr) {
    asm volatile("ldmatrix.sync.aligned.m8n8.x4.shared.b16 {%0,%1,%2,%3}, [%4];"
                 : "=r"(r[0]), "=r"(r[1]), "=r"(r[2]), "=r"(r[3]) : "r"(addr));
}
__device__ __forceinline__ void mma16816(float* d, const uint32_t* a, const uint32_t* b) {
    asm volatile("mma.sync.aligned.m16n8k16.row.col.f32.bf16.bf16.f32 "
                 "{%0,%1,%2,%3}, {%4,%5,%6,%7}, {%8,%9}, {%0,%1,%2,%3};"
                 : "+f"(d[0]), "+f"(d[1]), "+f"(d[2]), "+f"(d[3])
                 : "r"(a[0]), "r"(a[1]), "r"(a[2]), "r"(a[3]), "r"(b[0]), "r"(b[1]));
}

// ---------------- graph preprocessing ----------------
__global__ void k_init() {
    int i = blockIdx.x * blockDim.x + threadIdx.x;
    if (i < NN) { d_ecnt[i] = 0; d_cursor[i] = 0; }
}

__global__ void k_count(const int* __restrict__ dst) {
    int e = blockIdx.x * blockDim.x + threadIdx.x;
    if (e < NE) atomicAdd(&d_ecnt[dst[e]], 1);
}

__global__ void k_dinv() {
    int i = blockIdx.x * blockDim.x + threadIdx.x;
    if (i < NN) d_dinv[i] = rsqrtf((float)d_ecnt[i] + 1.0f);
}

__global__ void k_bsum() {
    __shared__ int s[256];
    int t = threadIdx.x;
    int i = blockIdx.x * 256 + t;
    s[t] = (i < NN) ? d_ecnt[i] : 0;
    __syncthreads();
    #pragma unroll
    for (int off = 128; off > 0; off >>= 1) {
        if (t < off) s[t] += s[t + off];
        __syncthreads();
    }
    if (t == 0) d_bsum[blockIdx.x] = s[0];
}

__global__ void k_bscan() {
    __shared__ int s[256];
    int t = threadIdx.x;
    int v0 = (t < NB) ? d_bsum[t] : 0;
    s[t] = v0;
    __syncthreads();
    #pragma unroll
    for (int off = 1; off < 256; off <<= 1) {
        int v = (t >= off) ? s[t - off] : 0;
        __syncthreads();
        s[t] += v;
        __syncthreads();
    }
    d_boff[t] = s[t] - v0;
}

__global__ void k_escan() {
    __shared__ int s[256];
    int t = threadIdx.x;
    int i = blockIdx.x * 256 + t;
    int v0 = (i < NN) ? d_ecnt[i] : 0;
    s[t] = v0;
    __syncthreads();
    #pragma unroll
    for (int off = 1; off < 256; off <<= 1) {
        int v = (t >= off) ? s[t - off] : 0;
        __syncthreads();
        s[t] += v;
        __syncthreads();
    }
    if (i < NN) d_rowptr[i + 1] = d_boff[blockIdx.x] + s[t];
    if (i == 0) d_rowptr[0] = 0;
}

__global__ void k_scatter(const int* __restrict__ src, const int* __restrict__ dst) {
    int e = blockIdx.x * blockDim.x + threadIdx.x;
    if (e >= NE) return;
    int s = src[e], d = dst[e];
    int pos = d_rowptr[d] + atomicAdd(&d_cursor[d], 1);
    d_csr_src[pos] = s;
    d_csr_dst[pos] = d;
    d_csr_norm[pos] = d_dinv[s] * d_dinv[d];
}

// ---------------- x0 = [nodes | cat_emb[cats]] ----------------
__global__ void k_embed(const float* __restrict__ nodes, const int* __restrict__ cats,
                        const float* __restrict__ emb) {
    int t = blockIdx.x * blockDim.x + threadIdx.x;
    if (t >= NN * 16) return;
    int node = t >> 4, j = t & 15;
    float4 v;
    if (j < 8) v = ((const float4*)nodes)[node * 8 + j];
    else       v = ((const float4*)emb)[(size_t)cats[node] * 8 + (j - 8)];
    ((float4*)d_x0)[node * 16 + j] = v;
}

// ---------------- prebuild We2^T hi/lo images ([n][k], stride 136) ----------------
__global__ void k_prepw(const float* __restrict__ We2) {
    int i = blockIdx.x * blockDim.x + threadIdx.x;
    if (i >= 16384) return;
    int n = i >> 7, k = i & 127;
    float w = We2[k * 128 + n];
    __nv_bfloat16 h = __float2bfloat16(w);
    __nv_bfloat16 l = __float2bfloat16(w - __bfloat162float(h));
    d_Whi[n * 136 + k] = h;
    d_Wlo[n * 136 + k] = l;
}

// ---------------- GEMM: Y[M,128] = X[M,K] @ (W0 - W1)[K,128] (+bias) ----------------
__global__ void __launch_bounds__(512)
gemm_n128(const float* __restrict__ X, int M, int K,
          const float* __restrict__ W0, const float* __restrict__ W1,
          const float* __restrict__ bias,
          float* __restrict__ Y) {
    extern __shared__ float sm[];
    float* sA = sm;
    float* sW = sm + 64 * 128;
    const int t = threadIdx.x;
    const int row0 = blockIdx.x * 128;
    const int tr = (t >> 4) << 2;
    const int tc = (t & 15) << 3;
    unsigned long long acc[4][4];
    #pragma unroll
    for (int i = 0; i < 4; i++)
        #pragma unroll
        for (int j = 0; j < 4; j++) acc[i][j] = 0ULL;

    for (int k0 = 0; k0 < K; k0 += 64) {
        #pragma unroll
        for (int i = t; i < 2048; i += 512) {
            int r = i & 127, c4 = i >> 7;
            float4 v = make_float4(0.f, 0.f, 0.f, 0.f);
            int gr = row0 + r;
            if (gr < M) v = *(const float4*)(X + (size_t)gr * K + k0 + (c4 << 2));
            int kk = c4 << 2;
            sA[(kk + 0) * 128 + r] = v.x;
            sA[(kk + 1) * 128 + r] = v.y;
            sA[(kk + 2) * 128 + r] = v.z;
            sA[(kk + 3) * 128 + r] = v.w;
        }
        #pragma unroll
        for (int i = t; i < 2048; i += 512) {
            int r = i >> 5, c4 = i & 31;
            float4 v = *(const float4*)(W0 + (size_t)(k0 + r) * 128 + (c4 << 2));
            if (W1) {
                float4 u = *(const float4*)(W1 + (size_t)(k0 + r) * 128 + (c4 << 2));
                v.x -= u.x; v.y -= u.y; v.z -= u.z; v.w -= u.w;
            }
            *(float4*)(sW + r * 128 + (c4 << 2)) = v;
        }
        __syncthreads();
        #pragma unroll 4
        for (int kk = 0; kk < 64; ++kk) {
            float4 av = *(const float4*)(sA + kk * 128 + tr);
            ulonglong2 w0 = *(const ulonglong2*)(sW + kk * 128 + tc);
            ulonglong2 w1 = *(const ulonglong2*)(sW + kk * 128 + tc + 4);
            unsigned long long a0 = dup2(av.x), a1 = dup2(av.y),
                               a2 = dup2(av.z), a3 = dup2(av.w);
            acc[0][0] = fma2(a0, w0.x, acc[0][0]);
            acc[0][1] = fma2(a0, w0.y, acc[0][1]);
            acc[0][2] = fma2(a0, w1.x, acc[0][2]);
            acc[0][3] = fma2(a0, w1.y, acc[0][3]);
            acc[1][0] = fma2(a1, w0.x, acc[1][0]);
            acc[1][1] = fma2(a1, w0.y, acc[1][1]);
            acc[1][2] = fma2(a1, w1.x, acc[1][2]);
            acc[1][3] = fma2(a1, w1.y, acc[1][3]);
            acc[2][0] = fma2(a2, w0.x, acc[2][0]);
            acc[2][1] = fma2(a2, w0.y, acc[2][1]);
            acc[2][2] = fma2(a2, w1.x, acc[2][2]);
            acc[2][3] = fma2(a2, w1.y, acc[2][3]);
            acc[3][0] = fma2(a3, w0.x, acc[3][0]);
            acc[3][1] = fma2(a3, w0.y, acc[3][1]);
            acc[3][2] = fma2(a3, w1.x, acc[3][2]);
            acc[3][3] = fma2(a3, w1.y, acc[3][3]);
        }
        __syncthreads();
    }
    float bv[8];
    if (bias) {
        *(float4*)(bv)     = *(const float4*)(bias + tc);
        *(float4*)(bv + 4) = *(const float4*)(bias + tc + 4);
    } else {
        #pragma unroll
        for (int j = 0; j < 8; j++) bv[j] = 0.f;
    }
    #pragma unroll
    for (int i = 0; i < 4; i++) {
        int gr = row0 + tr + i;
        if (gr < M) {
            float o[8];
            #pragma unroll
            for (int j = 0; j < 4; j++) {
                float2 f = unpack2(acc[i][j]);
                o[2 * j]     = f.x + bv[2 * j];
                o[2 * j + 1] = f.y + bv[2 * j + 1];
            }
            *(float4*)(Y + (size_t)gr * 128 + tc)     = *(float4*)(o);
            *(float4*)(Y + (size_t)gr * 128 + tc + 4) = *(float4*)(o + 4);
        }
    }
}

// ---------------- GCN aggregation ----------------
__global__ void gcn_agg(const float* __restrict__ H, const float* __restrict__ bias,
                        float* __restrict__ out) {
    int warp = threadIdx.x >> 5;
    int lane = threadIdx.x & 31;
    int node = blockIdx.x * 8 + warp;
    if (node >= NN) return;
    float dv = d_dinv[node];
    float sn = dv * dv;
    float4 acc = ((const float4*)H)[node * 32 + lane];
    acc.x *= sn; acc.y *= sn; acc.z *= sn; acc.w *= sn;
    int beg = d_rowptr[node], end = d_rowptr[node + 1];
    int e = beg;
    for (; e + 1 < end; e += 2) {
        int s0 = d_csr_src[e], s1 = d_csr_src[e + 1];
        float n0 = d_csr_norm[e], n1 = d_csr_norm[e + 1];
        float4 h0 = ((const float4*)H)[s0 * 32 + lane];
        float4 h1 = ((const float4*)H)[s1 * 32 + lane];
        acc.x = fmaf(h0.x, n0, acc.x); acc.y = fmaf(h0.y, n0, acc.y);
        acc.z = fmaf(h0.z, n0, acc.z); acc.w = fmaf(h0.w, n0, acc.w);
        acc.x = fmaf(h1.x, n1, acc.x); acc.y = fmaf(h1.y, n1, acc.y);
        acc.z = fmaf(h1.z, n1, acc.z); acc.w = fmaf(h1.w, n1, acc.w);
    }
    if (e < end) {
        int s = d_csr_src[e];
        float nm = d_csr_norm[e];
        float4 h = ((const float4*)H)[s * 32 + lane];
        acc.x = fmaf(h.x, nm, acc.x); acc.y = fmaf(h.y, nm, acc.y);
        acc.z = fmaf(h.z, nm, acc.z); acc.w = fmaf(h.w, nm, acc.w);
    }
    float4 b = ((const float4*)bias)[lane];
    float4 r;
    r.x = fmaxf(acc.x + b.x, 0.f);
    r.y = fmaxf(acc.y + b.y, 0.f);
    r.z = fmaxf(acc.z + b.z, 0.f);
    r.w = fmaxf(acc.w + b.w, 0.f);
    ((float4*)out)[node * 32 + lane] = r;
}

__global__ void k_zero(float* __restrict__ p, int n4) {
    int i = blockIdx.x * blockDim.x + threadIdx.x;
    if (i < n4) ((float4*)p)[i] = make_float4(0.f, 0.f, 0.f, 0.f);
}

// ---------------- EdgeConv via mma.sync bf16 3-MMA split ----------------
// block = 128 edges, 256 threads (8 warps). D[e][n] = relu(A[dst]+B[src]) @ We2;
// dst-run segmented max (+be2 after max) -> atomicMax into agg.
// smem: AHI[128][136]bf16, ALO, BHI, BLO (34816 B each, 139264 total).
// After MMA: result staged into sR[e][130]f32 (overlays AHI+ALO).
__global__ void __launch_bounds__(256)
edge_mlp_mma(const float* __restrict__ A, const float* __restrict__ Bm,
             const float* __restrict__ be2, float* __restrict__ agg) {
    extern __shared__ __align__(16) char smc[];
    __shared__ int sDst[128];
    __shared__ int sSrc[128];

    const int t = threadIdx.x;
    const int wid = t >> 5;
    const int lane = t & 31;
    const int e0 = blockIdx.x * 128;
    const uint32_t sb = smem_u32(smc);
    const uint32_t AHI = 0, ALO = 34816, BHI = 69632, BLO = 104448;

    if (t < 128) { sDst[t] = d_csr_dst[e0 + t]; sSrc[t] = d_csr_src[e0 + t]; }

    // async copy W hi/lo images (34816 B each = 2176 x 16B)
    {
        const uint4* gh = (const uint4*)d_Whi;
        const uint4* gl = (const uint4*)d_Wlo;
        for (int i = t; i < 2176; i += 256) {
            asm volatile("cp.async.cg.shared.global [%0], [%1], 16;"
                         :: "r"(sb + BHI + i * 16), "l"(gh + i));
            asm volatile("cp.async.cg.shared.global [%0], [%1], 16;"
                         :: "r"(sb + BLO + i * 16), "l"(gl + i));
        }
        asm volatile("cp.async.commit_group;");
    }
    __syncthreads();   // sDst/sSrc visible

    // gather relu(A[dst]+B[src]) -> AHI/ALO [e][k], row stride 272 B
    {
        int e = t & 127, hf = t >> 7;
        int d = sDst[e], s = sSrc[e];
        const float4* Ad = (const float4*)(A  + (size_t)d * 128) + hf * 16;
        const float4* Bs = (const float4*)(Bm + (size_t)s * 128) + hf * 16;
        uint32_t rowb = (uint32_t)e * 272u + (uint32_t)hf * 128u;
        char* pHi = smc + AHI;
        char* pLo = smc + ALO;
        #pragma unroll 4
        for (int seg = 0; seg < 16; ++seg) {
            float4 av = __ldg(Ad + seg);
            float4 bv = __ldg(Bs + seg);
            float v0 = fmaxf(av.x + bv.x, 0.f);
            float v1 = fmaxf(av.y + bv.y, 0.f);
            float v2 = fmaxf(av.z + bv.z, 0.f);
            float v3 = fmaxf(av.w + bv.w, 0.f);
            __nv_bfloat16 h0 = __float2bfloat16(v0), h1 = __float2bfloat16(v1);
            __nv_bfloat16 h2 = __float2bfloat16(v2), h3 = __float2bfloat16(v3);
            __nv_bfloat16 l0 = __float2bfloat16(v0 - __bfloat162float(h0));
            __nv_bfloat16 l1 = __float2bfloat16(v1 - __bfloat162float(h1));
            __nv_bfloat16 l2 = __float2bfloat16(v2 - __bfloat162float(h2));
            __nv_bfloat16 l3 = __float2bfloat16(v3 - __bfloat162float(h3));
            uint32_t ph01 = (uint32_t)__bfloat16_as_ushort(h0) | ((uint32_t)__bfloat16_as_ushort(h1) << 16);
            uint32_t ph23 = (uint32_t)__bfloat16_as_ushort(h2) | ((uint32_t)__bfloat16_as_ushort(h3) << 16);
            uint32_t pl01 = (uint32_t)__bfloat16_as_ushort(l0) | ((uint32_t)__bfloat16_as_ushort(l1) << 16);
            uint32_t pl23 = (uint32_t)__bfloat16_as_ushort(l2) | ((uint32_t)__bfloat16_as_ushort(l3) << 16);
            uint32_t off = rowb + (uint32_t)seg * 8u;
            *(uint32_t*)(pHi + off)     = ph01;
            *(uint32_t*)(pHi + off + 4) = ph23;
            *(uint32_t*)(pLo + off)     = pl01;
            *(uint32_t*)(pLo + off + 4) = pl23;
        }
    }
    asm volatile("cp.async.wait_group 0;" ::: "memory");
    __syncthreads();

    // warp tile: rows [wm, wm+64), cols [wn, wn+32)
    const int wm = (wid & 1) * 64;
    const int wn = (wid >> 1) * 32;
    const int lid8 = lane & 7;
    const int grp = lane >> 3;

    // A lane addresses: matrices m0..7@k0, m8..15@k0, m0..7@k8, m8..15@k8
    uint32_t aAddrHi[4], aAddrLo[4];
    {
        uint32_t row = (uint32_t)(wm + (grp & 1) * 8 + lid8);
        uint32_t col = (uint32_t)((grp >> 1) * 8);
        #pragma unroll
        for (int mt = 0; mt < 4; ++mt) {
            uint32_t byteOff = (row + mt * 16) * 272u + col * 2u;
            aAddrHi[mt] = sb + AHI + byteOff;
            aAddrLo[mt] = sb + ALO + byteOff;
        }
    }
    // B lane addresses: matrices n0..7@k0, n0..7@k8, n8..15@k0, n8..15@k8
    uint32_t bAddrHi[2], bAddrLo[2];
    {
        uint32_t row = (uint32_t)(wn + (grp >> 1) * 8 + lid8);
        uint32_t col = (uint32_t)((grp & 1) * 8);
        #pragma unroll
        for (int p = 0; p < 2; ++p) {
            uint32_t byteOff = (row + p * 16) * 272u + col * 2u;
            bAddrHi[p] = sb + BHI + byteOff;
            bAddrLo[p] = sb + BLO + byteOff;
        }
    }

    float ac[4][4][4];
    #pragma unroll
    for (int i = 0; i < 4; i++)
        #pragma unroll
        for (int j = 0; j < 4; j++)
            #pragma unroll
            for (int q = 0; q < 4; q++) ac[i][j][q] = 0.f;

    #pragma unroll
    for (int kt = 0; kt < 8; ++kt) {
        uint32_t kb = kt * 32u;   // 16 elems * 2B
        uint32_t aHi[4][4], aLo[4][4];
        uint32_t bHi[4][2], bLo[4][2];
        #pragma unroll
        for (int mt = 0; mt < 4; ++mt) {
            ldm_x4(aHi[mt], aAddrHi[mt] + kb);
            ldm_x4(aLo[mt], aAddrLo[mt] + kb);
        }
        #pragma unroll
        for (int p = 0; p < 2; ++p) {
            uint32_t r[4];
            ldm_x4(r, bAddrHi[p] + kb);
            bHi[2 * p][0] = r[0]; bHi[2 * p][1] = r[1];
            bHi[2 * p + 1][0] = r[2]; bHi[2 * p + 1][1] = r[3];
            ldm_x4(r, bAddrLo[p] + kb);
            bLo[2 * p][0] = r[0]; bLo[2 * p][1] = r[1];
            bLo[2 * p + 1][0] = r[2]; bLo[2 * p + 1][1] = r[3];
        }
        #pragma unroll
        for (int mt = 0; mt < 4; ++mt)
            #pragma unroll
            for (int nt = 0; nt < 4; ++nt) {
                mma16816(ac[mt][nt], aHi[mt], bHi[nt]);
                mma16816(ac[mt][nt], aHi[mt], bLo[nt]);
                mma16816(ac[mt][nt], aLo[mt], bHi[nt]);
            }
    }
    __syncthreads();   // everyone done reading A/B tiles

    // stage D into sR[e][130] (overlays AHI+ALO: 128*130*4 = 66560 <= 69632)
    float* sR = (float*)smc;
    {
        int rr = lane >> 2;
        int cc = (lane & 3) * 2;
        #pragma unroll
        for (int mt = 0; mt < 4; ++mt)
            #pragma unroll
            for (int nt = 0; nt < 4; ++nt) {
                int r0 = wm + mt * 16 + rr;
                int c = wn + nt * 8 + cc;
                *(float2*)&sR[r0 * 130 + c]       = make_float2(ac[mt][nt][0], ac[mt][nt][1]);
                *(float2*)&sR[(r0 + 8) * 130 + c] = make_float2(ac[mt][nt][2], ac[mt][nt][3]);
            }
    }
    __syncthreads();

    // per-(col, half) dst-run reduction; bias added AFTER max (constant per col)
    {
        int col = t >> 1;
        int q = t & 1;
        int eb = q * 64;
        float bias = __ldg(be2 + col);
        int cur = sDst[eb];
        float m = sR[eb * 130 + col];
        #pragma unroll 4
        for (int i = 1; i < 64; ++i) {
            int e = eb + i;
            int d = sDst[e];
            float v = sR[e * 130 + col];
            if (d != cur) {
                float mb = m + bias;
                if (mb > 0.f) atomicMax((int*)(agg + (size_t)cur * 128 + col), __float_as_int(mb));
                cur = d; m = v;
            } else {
                m = fmaxf(m, v);
            }
        }
        float mb = m + bias;
        if (mb > 0.f) atomicMax((int*)(agg + (size_t)cur * 128 + col), __float_as_int(mb));
    }
}

// ---------------- pooling ----------------
__global__ void k_zero_pool() {
    int i = blockIdx.x * blockDim.x + threadIdx.x;
    if (i < NG * 128) { d_gmax[i] = 0.f; d_gsum[i] = 0.f; }
    if (i < NG) d_gcnt[i] = 0.f;
}

__global__ void __launch_bounds__(256)
k_pool2(const int* __restrict__ batch, const float* __restrict__ X) {
    int base = blockIdx.x * 128;
    int ch = threadIdx.x & 127;
    int half = threadIdx.x >> 7;
    int cur = -1;
    float vmax = 0.f, vsum = 0.f;
    for (int i = half; i < 128; i += 2) {
        int n = base + i;
        if (n >= NN) break;
        int g = batch[n];
        if (g != cur) {
            if (cur >= 0) {
                atomicAdd(&d_gsum[cur * 128 + ch], vsum);
                if (vmax > 0.f) atomicMax((int*)&d_gmax[cur * 128 + ch], __float_as_int(vmax));
            }
            cur = g; vmax = 0.f; vsum = 0.f;
        }
        float v = X[(size_t)n * 128 + ch];
        vsum += v;
        vmax = fmaxf(vmax, v);
    }
    if (cur >= 0) {
        atomicAdd(&d_gsum[cur * 128 + ch], vsum);
        if (vmax > 0.f) atomicMax((int*)&d_gmax[cur * 128 + ch], __float_as_int(vmax));
    }
    if (threadIdx.x == 0) {
        int c = -1; float cnt = 0.f;
        for (int i = 0; i < 128; ++i) {
            int n = base + i;
            if (n >= NN) break;
            int g = batch[n];
            if (g != c) {
                if (c >= 0) atomicAdd(&d_gcnt[c], cnt);
                c = g; cnt = 0.f;
            }
            cnt += 1.f;
        }
        if (c >= 0) atomicAdd(&d_gcnt[c], cnt);
    }
}

__global__ void k_pool_fin() {
    int t = blockIdx.x * blockDim.x + threadIdx.x;
    if (t >= NG * 256) return;
    int g = t >> 8, c = t & 255;
    float v;
    if (c < 128) v = d_gmax[g * 128 + c];
    else         v = d_gsum[g * 128 + c - 128] / fmaxf(d_gcnt[g], 1.0f);
    d_g[t] = v;
}

// ---------------- head ----------------
__global__ void head_gemm(const float* __restrict__ in, const float* __restrict__ W,
                          const float* __restrict__ b, float* __restrict__ out) {
    __shared__ float srow[256];
    int t = threadIdx.x;
    int g = blockIdx.x;
    srow[t] = in[g * 256 + t];
    __syncthreads();
    float acc = b[t];
    #pragma unroll 8
    for (int k = 0; k < 256; ++k) acc = fmaf(srow[k], W[k * 256 + t], acc);
    out[g * 256 + t] = fmaxf(acc, 0.f);
}

// ---------------- launch ----------------
extern "C" void kernel_launch(void* const* d_in, const int* in_sizes, int n_in,
                              void* d_out, int out_size) {
    const float* nodes   = (const float*)d_in[0];
    const int*   cats    = (const int*)d_in[1];
    const int*   ei      = (const int*)d_in[2];
    const int*   batch   = (const int*)d_in[3];
    const float* cat_emb = (const float*)d_in[4];
    const float* W1  = (const float*)d_in[5];
    const float* b1  = (const float*)d_in[6];
    const float* W2  = (const float*)d_in[7];
    const float* b2  = (const float*)d_in[8];
    const float* W3  = (const float*)d_in[9];
    const float* b3  = (const float*)d_in[10];
    const float* We1 = (const float*)d_in[11];
    const float* be1 = (const float*)d_in[12];
    const float* We2 = (const float*)d_in[13];
    const float* be2 = (const float*)d_in[14];
    const float* Wf1 = (const float*)d_in[15];
    const float* bf1 = (const float*)d_in[16];
    const float* Wf2 = (const float*)d_in[17];
    const float* bf2 = (const float*)d_in[18];
    const int* src = ei;
    const int* dst = ei + NE;
    float* out = (float*)d_out;

    const int EDGE_SMEM = 139264;  // 4 x 34816

    cudaFuncSetAttribute(gemm_n128,    cudaFuncAttributeMaxDynamicSharedMemorySize, 65536);
    cudaFuncSetAttribute(edge_mlp_mma, cudaFuncAttributeMaxDynamicSharedMemorySize, EDGE_SMEM);

    float *bufA, *bufB, *bufC, *x0, *g, *h1;
    cudaGetSymbolAddress((void**)&bufA, d_bufA);
    cudaGetSymbolAddress((void**)&bufB, d_bufB);
    cudaGetSymbolAddress((void**)&bufC, d_bufC);
    cudaGetSymbolAddress((void**)&x0,   d_x0);
    cudaGetSymbolAddress((void**)&g,    d_g);
    cudaGetSymbolAddress((void**)&h1,   d_h1);

    // CSR + norms
    k_init<<<(NN + 255) / 256, 256>>>();
    k_count<<<(NE + 255) / 256, 256>>>(dst);
    k_dinv<<<(NN + 255) / 256, 256>>>();
    k_bsum<<<NB, 256>>>();
    k_bscan<<<1, 256>>>();
    k_escan<<<NB, 256>>>();
    k_scatter<<<(NE + 255) / 256, 256>>>(src, dst);

    // x0 = [nodes | emb]; We2^T hi/lo images
    k_embed<<<(NN * 16 + 255) / 256, 256>>>(nodes, cats, cat_emb);
    k_prepw<<<64, 256>>>(We2);

    const int gg = (NN + 127) / 128;  // 391
    // GCN 1
    gemm_n128<<<gg, 512, 65536>>>(x0, NN, 64, W1, nullptr, nullptr, bufA);
    gcn_agg<<<(NN + 7) / 8, 256>>>(bufA, b1, bufB);
    // GCN 2
    gemm_n128<<<gg, 512, 65536>>>(bufB, NN, 128, W2, nullptr, nullptr, bufA);
    gcn_agg<<<(NN + 7) / 8, 256>>>(bufA, b2, bufB);
    // GCN 3
    gemm_n128<<<gg, 512, 65536>>>(bufB, NN, 128, W3, nullptr, nullptr, bufA);
    gcn_agg<<<(NN + 7) / 8, 256>>>(bufA, b3, bufC);   // x3 -> bufC

    // EdgeConv precompute: A = x3 @ (We1_top - We1_bot) + be1 ; B = x3 @ We1_bot
    gemm_n128<<<gg, 512, 65536>>>(bufC, NN, 128, We1, We1 + 128 * 128, be1, bufA);
    gemm_n128<<<gg, 512, 65536>>>(bufC, NN, 128, We1 + 128 * 128, nullptr, nullptr, bufB);

    // EdgeConv per-edge MLP + segment max via mma.sync
    k_zero<<<(NN * 32 + 255) / 256, 256>>>(bufC, NN * 32);
    edge_mlp_mma<<<NE / 128, 256, EDGE_SMEM>>>(bufA, bufB, be2, bufC);

    // pooling
    k_zero_pool<<<(NG * 128 + 255) / 256, 256>>>();
    k_pool2<<<(NN + 127) / 128, 256>>>(batch, bufC);
    k_pool_fin<<<(NG * 256 + 255) / 256, 256>>>();

    // head
    head_gemm<<<NG, 256>>>(g, Wf1, bf1, h1);
    head_gemm<<<NG, 256>>>(h1, Wf2, bf2, out);
}

// round 7
// speedup vs baseline: 2.6594x; 1.2560x over previous
#include <cuda_runtime.h>
#include <cuda_bf16.h>
#include <cstddef>
#include <cstdint>

#define NN 50000
#define NE 800000
#define NG 64
#define NB 196   // ceil(NN/256)

// ---------------- scratch (__device__ globals; no allocation allowed) ----------------
__device__ __align__(16) float d_x0[NN * 64];
__device__ __align__(16) float d_bufA[NN * 128];
__device__ __align__(16) float d_bufB[NN * 128];
__device__ __align__(16) float d_bufC[NN * 128];
__device__ __align__(16) float d_dinv[NN];
__device__ int d_ecnt[NN];
__device__ int d_cursor[NN];
__device__ int d_rowptr[NN + 1];
__device__ int d_bsum[256];
__device__ int d_boff[256];
__device__ int d_csr_src[NE];
__device__ int d_csr_dst[NE];
__device__ __align__(16) float d_csr_norm[NE];
__device__ __align__(16) float d_gmax[NG * 128];
__device__ __align__(16) float d_gsum[NG * 128];
__device__ float d_gcnt[NG];
__device__ __align__(16) float d_g[NG * 256];
__device__ __align__(16) float d_h1[NG * 256];
// prebuilt We2^T bf16 hi/lo images: [n][k] rows, stride 136 elems (272 B)
__device__ __align__(16) __nv_bfloat16 d_Whi[128 * 136];
__device__ __align__(16) __nv_bfloat16 d_Wlo[128 * 136];
// prebuilt node-GEMM weight images: 5 x [128][136]  (W1,W2,W3,Wd=We1t-We1b,Wb=We1b)
__device__ __align__(16) __nv_bfloat16 d_gWhi[5 * 128 * 136];
__device__ __align__(16) __nv_bfloat16 d_gWlo[5 * 128 * 136];

#define WIMG (128 * 136)

// ---------------- mma.sync helpers ----------------
__device__ __forceinline__ uint32_t smem_u32(const void* p) {
    uint32_t a;
    asm("{ .reg .u64 t; cvta.to.shared.u64 t, %1; cvt.u32.u64 %0, t; }" : "=r"(a) : "l"(p));
    return a;
}
__device__ __forceinline__ void ldm_x4(uint32_t* r, uint32_t addr) {
    asm volatile("ldmatrix.sync.aligned.m8n8.x4.shared.b16 {%0,%1,%2,%3}, [%4];"
                 : "=r"(r[0]), "=r"(r[1]), "=r"(r[2]), "=r"(r[3]) : "r"(addr));
}
__device__ __forceinline__ void mma16816(float* d, const uint32_t* a, const uint32_t* b) {
    asm volatile("mma.sync.aligned.m16n8k16.row.col.f32.bf16.bf16.f32 "
                 "{%0,%1,%2,%3}, {%4,%5,%6,%7}, {%8,%9}, {%0,%1,%2,%3};"
                 : "+f"(d[0]), "+f"(d[1]), "+f"(d[2]), "+f"(d[3])
                 : "r"(a[0]), "r"(a[1]), "r"(a[2]), "r"(a[3]), "r"(b[0]), "r"(b[1]));
}
__device__ __forceinline__ void split_pack(float v0, float v1, uint32_t& hi, uint32_t& lo) {
    __nv_bfloat16 h0 = __float2bfloat16(v0), h1 = __float2bfloat16(v1);
    __nv_bfloat16 l0 = __float2bfloat16(v0 - __bfloat162float(h0));
    __nv_bfloat16 l1 = __float2bfloat16(v1 - __bfloat162float(h1));
    hi = (uint32_t)__bfloat16_as_ushort(h0) | ((uint32_t)__bfloat16_as_ushort(h1) << 16);
    lo = (uint32_t)__bfloat16_as_ushort(l0) | ((uint32_t)__bfloat16_as_ushort(l1) << 16);
}

// ---------------- graph preprocessing ----------------
__global__ void k_init() {
    int i = blockIdx.x * blockDim.x + threadIdx.x;
    if (i < NN) { d_ecnt[i] = 0; d_cursor[i] = 0; }
}

__global__ void k_count(const int* __restrict__ dst) {
    int e = blockIdx.x * blockDim.x + threadIdx.x;
    if (e < NE) atomicAdd(&d_ecnt[dst[e]], 1);
}

__global__ void k_dinv() {
    int i = blockIdx.x * blockDim.x + threadIdx.x;
    if (i < NN) d_dinv[i] = rsqrtf((float)d_ecnt[i] + 1.0f);
}

__global__ void k_bsum() {
    __shared__ int s[256];
    int t = threadIdx.x;
    int i = blockIdx.x * 256 + t;
    s[t] = (i < NN) ? d_ecnt[i] : 0;
    __syncthreads();
    #pragma unroll
    for (int off = 128; off > 0; off >>= 1) {
        if (t < off) s[t] += s[t + off];
        __syncthreads();
    }
    if (t == 0) d_bsum[blockIdx.x] = s[0];
}

__global__ void k_bscan() {
    __shared__ int s[256];
    int t = threadIdx.x;
    int v0 = (t < NB) ? d_bsum[t] : 0;
    s[t] = v0;
    __syncthreads();
    #pragma unroll
    for (int off = 1; off < 256; off <<= 1) {
        int v = (t >= off) ? s[t - off] : 0;
        __syncthreads();
        s[t] += v;
        __syncthreads();
    }
    d_boff[t] = s[t] - v0;
}

__global__ void k_escan() {
    __shared__ int s[256];
    int t = threadIdx.x;
    int i = blockIdx.x * 256 + t;
    int v0 = (i < NN) ? d_ecnt[i] : 0;
    s[t] = v0;
    __syncthreads();
    #pragma unroll
    for (int off = 1; off < 256; off <<= 1) {
        int v = (t >= off) ? s[t - off] : 0;
        __syncthreads();
        s[t] += v;
        __syncthreads();
    }
    if (i < NN) d_rowptr[i + 1] = d_boff[blockIdx.x] + s[t];
    if (i == 0) d_rowptr[0] = 0;
}

__global__ void k_scatter(const int* __restrict__ src, const int* __restrict__ dst) {
    int e = blockIdx.x * blockDim.x + threadIdx.x;
    if (e >= NE) return;
    int s = src[e], d = dst[e];
    int pos = d_rowptr[d] + atomicAdd(&d_cursor[d], 1);
    d_csr_src[pos] = s;
    d_csr_dst[pos] = d;
    d_csr_norm[pos] = d_dinv[s] * d_dinv[d];
}

// ---------------- x0 = [nodes | cat_emb[cats]] ----------------
__global__ void k_embed(const float* __restrict__ nodes, const int* __restrict__ cats,
                        const float* __restrict__ emb) {
    int t = blockIdx.x * blockDim.x + threadIdx.x;
    if (t >= NN * 16) return;
    int node = t >> 4, j = t & 15;
    float4 v;
    if (j < 8) v = ((const float4*)nodes)[node * 8 + j];
    else       v = ((const float4*)emb)[(size_t)cats[node] * 8 + (j - 8)];
    ((float4*)d_x0)[node * 16 + j] = v;
}

// ---------------- prebuild We2^T hi/lo image ([n][k], stride 136) ----------------
__global__ void k_prepw(const float* __restrict__ We2) {
    int i = blockIdx.x * blockDim.x + threadIdx.x;
    if (i >= 16384) return;
    int n = i >> 7, k = i & 127;
    float w = We2[k * 128 + n];
    __nv_bfloat16 h = __float2bfloat16(w);
    __nv_bfloat16 l = __float2bfloat16(w - __bfloat162float(h));
    d_Whi[n * 136 + k] = h;
    d_Wlo[n * 136 + k] = l;
}

// ---------------- prebuild node-GEMM weight images ----------------
// img0: W1 (K=64); img1: W2; img2: W3; img3: We1_top - We1_bot; img4: We1_bot
__global__ void k_prepw_gen(const float* __restrict__ W1, const float* __restrict__ W2,
                            const float* __restrict__ W3, const float* __restrict__ We1) {
    int i = blockIdx.x * blockDim.x + threadIdx.x;
    if (i >= 5 * 16384) return;
    int img = i >> 14;
    int idx = i & 16383;
    int n = idx >> 7, k = idx & 127;
    float w;
    if (img == 0) {
        if (k >= 64) return;
        w = W1[k * 128 + n];
    } else if (img == 1) {
        w = W2[k * 128 + n];
    } else if (img == 2) {
        w = W3[k * 128 + n];
    } else if (img == 3) {
        w = We1[k * 128 + n] - We1[(k + 128) * 128 + n];
    } else {
        w = We1[(k + 128) * 128 + n];
    }
    __nv_bfloat16 h = __float2bfloat16(w);
    __nv_bfloat16 l = __float2bfloat16(w - __bfloat162float(h));
    d_gWhi[img * WIMG + n * 136 + k] = h;
    d_gWlo[img * WIMG + n * 136 + k] = l;
}

// ---------------- node GEMM via mma.sync bf16 3-split ----------------
// Y[M,128] = X[M,Kin] @ W  (+bias). 128 rows/block, 256 threads (8 warps).
__global__ void __launch_bounds__(256)
gemm_mma(const float* __restrict__ X, int M, int Kin,
         const __nv_bfloat16* __restrict__ gWhi, const __nv_bfloat16* __restrict__ gWlo,
         const float* __restrict__ bias, float* __restrict__ Y) {
    extern __shared__ __align__(16) char smc[];
    const int t = threadIdx.x;
    const int wid = t >> 5;
    const int lane = t & 31;
    const int row0 = blockIdx.x * 128;
    const uint32_t sb = smem_u32(smc);
    const uint32_t XHI = 0, XLO = 34816, WHI = 69632, WLO = 104448;

    // async copy W images
    {
        const uint4* gh = (const uint4*)gWhi;
        const uint4* gl = (const uint4*)gWlo;
        for (int i = t; i < 2176; i += 256) {
            asm volatile("cp.async.cg.shared.global [%0], [%1], 16;"
                         :: "r"(sb + WHI + i * 16), "l"(gh + i));
            asm volatile("cp.async.cg.shared.global [%0], [%1], 16;"
                         :: "r"(sb + WLO + i * 16), "l"(gl + i));
        }
        asm volatile("cp.async.commit_group;");
    }

    // gather X rows -> XHI/XLO [r][k], row stride 272 B
    {
        int r = t & 127, hf = t >> 7;
        int gr = row0 + r;
        const float4* Xr = (const float4*)(X + (size_t)gr * Kin);
        int ns = Kin >> 3;               // float4 segs per half
        char* pHi = smc + XHI;
        char* pLo = smc + XLO;
        uint32_t rowb = (uint32_t)r * 272u;
        if (gr < M) {
            #pragma unroll 4
            for (int s = hf * ns; s < (hf + 1) * ns; ++s) {
                float4 v = __ldg(Xr + s);
                uint32_t hi0, lo0, hi1, lo1;
                split_pack(v.x, v.y, hi0, lo0);
                split_pack(v.z, v.w, hi1, lo1);
                uint32_t off = rowb + (uint32_t)s * 8u;
                *(uint32_t*)(pHi + off)     = hi0;
                *(uint32_t*)(pHi + off + 4) = hi1;
                *(uint32_t*)(pLo + off)     = lo0;
                *(uint32_t*)(pLo + off + 4) = lo1;
            }
        } else {
            for (int s = hf * ns; s < (hf + 1) * ns; ++s) {
                uint32_t off = rowb + (uint32_t)s * 8u;
                *(uint64_t*)(pHi + off) = 0ULL;
                *(uint64_t*)(pLo + off) = 0ULL;
            }
        }
    }
    asm volatile("cp.async.wait_group 0;" ::: "memory");
    __syncthreads();

    const int wm = (wid & 1) * 64;
    const int wn = (wid >> 1) * 32;
    const int lid8 = lane & 7;
    const int grp = lane >> 3;

    uint32_t aAddrHi[4], aAddrLo[4];
    {
        uint32_t row = (uint32_t)(wm + (grp & 1) * 8 + lid8);
        uint32_t col = (uint32_t)((grp >> 1) * 8);
        #pragma unroll
        for (int mt = 0; mt < 4; ++mt) {
            uint32_t byteOff = (row + mt * 16) * 272u + col * 2u;
            aAddrHi[mt] = sb + XHI + byteOff;
            aAddrLo[mt] = sb + XLO + byteOff;
        }
    }
    uint32_t bAddrHi[2], bAddrLo[2];
    {
        uint32_t row = (uint32_t)(wn + (grp >> 1) * 8 + lid8);
        uint32_t col = (uint32_t)((grp & 1) * 8);
        #pragma unroll
        for (int p = 0; p < 2; ++p) {
            uint32_t byteOff = (row + p * 16) * 272u + col * 2u;
            bAddrHi[p] = sb + WHI + byteOff;
            bAddrLo[p] = sb + WLO + byteOff;
        }
    }

    float ac[4][4][4];
    #pragma unroll
    for (int i = 0; i < 4; i++)
        #pragma unroll
        for (int j = 0; j < 4; j++)
            #pragma unroll
            for (int q = 0; q < 4; q++) ac[i][j][q] = 0.f;

    const int nkt = Kin >> 4;
    for (int kt = 0; kt < nkt; ++kt) {
        uint32_t kb = kt * 32u;
        uint32_t aHi[4][4], aLo[4][4];
        uint32_t bHi[4][2], bLo[4][2];
        #pragma unroll
        for (int mt = 0; mt < 4; ++mt) {
            ldm_x4(aHi[mt], aAddrHi[mt] + kb);
            ldm_x4(aLo[mt], aAddrLo[mt] + kb);
        }
        #pragma unroll
        for (int p = 0; p < 2; ++p) {
            uint32_t r[4];
            ldm_x4(r, bAddrHi[p] + kb);
            bHi[2 * p][0] = r[0]; bHi[2 * p][1] = r[1];
            bHi[2 * p + 1][0] = r[2]; bHi[2 * p + 1][1] = r[3];
            ldm_x4(r, bAddrLo[p] + kb);
            bLo[2 * p][0] = r[0]; bLo[2 * p][1] = r[1];
            bLo[2 * p + 1][0] = r[2]; bLo[2 * p + 1][1] = r[3];
        }
        #pragma unroll
        for (int mt = 0; mt < 4; ++mt)
            #pragma unroll
            for (int nt = 0; nt < 4; ++nt) {
                mma16816(ac[mt][nt], aHi[mt], bHi[nt]);
                mma16816(ac[mt][nt], aHi[mt], bLo[nt]);
                mma16816(ac[mt][nt], aLo[mt], bHi[nt]);
            }
    }

    // epilogue: write D (+bias) to Y
    {
        int rr = lane >> 2;
        int cc = (lane & 3) * 2;
        #pragma unroll
        for (int nt = 0; nt < 4; ++nt) {
            int c = wn + nt * 8 + cc;
            float b0 = bias ? __ldg(bias + c)     : 0.f;
            float b1 = bias ? __ldg(bias + c + 1) : 0.f;
            #pragma unroll
            for (int mt = 0; mt < 4; ++mt) {
                int r0 = wm + mt * 16 + rr;
                int gr0 = row0 + r0;
                int gr1 = gr0 + 8;
                if (gr0 < M)
                    *(float2*)&Y[(size_t)gr0 * 128 + c] =
                        make_float2(ac[mt][nt][0] + b0, ac[mt][nt][1] + b1);
                if (gr1 < M)
                    *(float2*)&Y[(size_t)gr1 * 128 + c] =
                        make_float2(ac[mt][nt][2] + b0, ac[mt][nt][3] + b1);
            }
        }
    }
}

// ---------------- GCN aggregation ----------------
__global__ void gcn_agg(const float* __restrict__ H, const float* __restrict__ bias,
                        float* __restrict__ out) {
    int warp = threadIdx.x >> 5;
    int lane = threadIdx.x & 31;
    int node = blockIdx.x * 8 + warp;
    if (node >= NN) return;
    float dv = d_dinv[node];
    float sn = dv * dv;
    float4 acc = ((const float4*)H)[node * 32 + lane];
    acc.x *= sn; acc.y *= sn; acc.z *= sn; acc.w *= sn;
    int beg = d_rowptr[node], end = d_rowptr[node + 1];
    int e = beg;
    for (; e + 1 < end; e += 2) {
        int s0 = d_csr_src[e], s1 = d_csr_src[e + 1];
        float n0 = d_csr_norm[e], n1 = d_csr_norm[e + 1];
        float4 h0 = ((const float4*)H)[s0 * 32 + lane];
        float4 h1 = ((const float4*)H)[s1 * 32 + lane];
        acc.x = fmaf(h0.x, n0, acc.x); acc.y = fmaf(h0.y, n0, acc.y);
        acc.z = fmaf(h0.z, n0, acc.z); acc.w = fmaf(h0.w, n0, acc.w);
        acc.x = fmaf(h1.x, n1, acc.x); acc.y = fmaf(h1.y, n1, acc.y);
        acc.z = fmaf(h1.z, n1, acc.z); acc.w = fmaf(h1.w, n1, acc.w);
    }
    if (e < end) {
        int s = d_csr_src[e];
        float nm = d_csr_norm[e];
        float4 h = ((const float4*)H)[s * 32 + lane];
        acc.x = fmaf(h.x, nm, acc.x); acc.y = fmaf(h.y, nm, acc.y);
        acc.z = fmaf(h.z, nm, acc.z); acc.w = fmaf(h.w, nm, acc.w);
    }
    float4 b = ((const float4*)bias)[lane];
    float4 r;
    r.x = fmaxf(acc.x + b.x, 0.f);
    r.y = fmaxf(acc.y + b.y, 0.f);
    r.z = fmaxf(acc.z + b.z, 0.f);
    r.w = fmaxf(acc.w + b.w, 0.f);
    ((float4*)out)[node * 32 + lane] = r;
}

__global__ void k_zero(float* __restrict__ p, int n4) {
    int i = blockIdx.x * blockDim.x + threadIdx.x;
    if (i < n4) ((float4*)p)[i] = make_float4(0.f, 0.f, 0.f, 0.f);
}

// ---------------- EdgeConv via mma.sync bf16 3-MMA split ----------------
__global__ void __launch_bounds__(256)
edge_mlp_mma(const float* __restrict__ A, const float* __restrict__ Bm,
             const float* __restrict__ be2, float* __restrict__ agg) {
    extern __shared__ __align__(16) char smc[];
    __shared__ int sDst[128];
    __shared__ int sSrc[128];

    const int t = threadIdx.x;
    const int wid = t >> 5;
    const int lane = t & 31;
    const int e0 = blockIdx.x * 128;
    const uint32_t sb = smem_u32(smc);
    const uint32_t AHI = 0, ALO = 34816, BHI = 69632, BLO = 104448;

    if (t < 128) { sDst[t] = d_csr_dst[e0 + t]; sSrc[t] = d_csr_src[e0 + t]; }

    {
        const uint4* gh = (const uint4*)d_Whi;
        const uint4* gl = (const uint4*)d_Wlo;
        for (int i = t; i < 2176; i += 256) {
            asm volatile("cp.async.cg.shared.global [%0], [%1], 16;"
                         :: "r"(sb + BHI + i * 16), "l"(gh + i));
            asm volatile("cp.async.cg.shared.global [%0], [%1], 16;"
                         :: "r"(sb + BLO + i * 16), "l"(gl + i));
        }
        asm volatile("cp.async.commit_group;");
    }
    __syncthreads();

    {
        int e = t & 127, hf = t >> 7;
        int d = sDst[e], s = sSrc[e];
        const float4* Ad = (const float4*)(A  + (size_t)d * 128) + hf * 16;
        const float4* Bs = (const float4*)(Bm + (size_t)s * 128) + hf * 16;
        uint32_t rowb = (uint32_t)e * 272u + (uint32_t)hf * 128u;
        char* pHi = smc + AHI;
        char* pLo = smc + ALO;
        #pragma unroll 4
        for (int seg = 0; seg < 16; ++seg) {
            float4 av = __ldg(Ad + seg);
            float4 bv = __ldg(Bs + seg);
            float v0 = fmaxf(av.x + bv.x, 0.f);
            float v1 = fmaxf(av.y + bv.y, 0.f);
            float v2 = fmaxf(av.z + bv.z, 0.f);
            float v3 = fmaxf(av.w + bv.w, 0.f);
            uint32_t hi0, lo0, hi1, lo1;
            split_pack(v0, v1, hi0, lo0);
            split_pack(v2, v3, hi1, lo1);
            uint32_t off = rowb + (uint32_t)seg * 8u;
            *(uint32_t*)(pHi + off)     = hi0;
            *(uint32_t*)(pHi + off + 4) = hi1;
            *(uint32_t*)(pLo + off)     = lo0;
            *(uint32_t*)(pLo + off + 4) = lo1;
        }
    }
    asm volatile("cp.async.wait_group 0;" ::: "memory");
    __syncthreads();

    const int wm = (wid & 1) * 64;
    const int wn = (wid >> 1) * 32;
    const int lid8 = lane & 7;
    const int grp = lane >> 3;

    uint32_t aAddrHi[4], aAddrLo[4];
    {
        uint32_t row = (uint32_t)(wm + (grp & 1) * 8 + lid8);
        uint32_t col = (uint32_t)((grp >> 1) * 8);
        #pragma unroll
        for (int mt = 0; mt < 4; ++mt) {
            uint32_t byteOff = (row + mt * 16) * 272u + col * 2u;
            aAddrHi[mt] = sb + AHI + byteOff;
            aAddrLo[mt] = sb + ALO + byteOff;
        }
    }
    uint32_t bAddrHi[2], bAddrLo[2];
    {
        uint32_t row = (uint32_t)(wn + (grp >> 1) * 8 + lid8);
        uint32_t col = (uint32_t)((grp & 1) * 8);
        #pragma unroll
        for (int p = 0; p < 2; ++p) {
            uint32_t byteOff = (row + p * 16) * 272u + col * 2u;
            bAddrHi[p] = sb + BHI + byteOff;
            bAddrLo[p] = sb + BLO + byteOff;
        }
    }

    float ac[4][4][4];
    #pragma unroll
    for (int i = 0; i < 4; i++)
        #pragma unroll
        for (int j = 0; j < 4; j++)
            #pragma unroll
            for (int q = 0; q < 4; q++) ac[i][j][q] = 0.f;

    #pragma unroll
    for (int kt = 0; kt < 8; ++kt) {
        uint32_t kb = kt * 32u;
        uint32_t aHi[4][4], aLo[4][4];
        uint32_t bHi[4][2], bLo[4][2];
        #pragma unroll
        for (int mt = 0; mt < 4; ++mt) {
            ldm_x4(aHi[mt], aAddrHi[mt] + kb);
            ldm_x4(aLo[mt], aAddrLo[mt] + kb);
        }
        #pragma unroll
        for (int p = 0; p < 2; ++p) {
            uint32_t r[4];
            ldm_x4(r, bAddrHi[p] + kb);
            bHi[2 * p][0] = r[0]; bHi[2 * p][1] = r[1];
            bHi[2 * p + 1][0] = r[2]; bHi[2 * p + 1][1] = r[3];
            ldm_x4(r, bAddrLo[p] + kb);
            bLo[2 * p][0] = r[0]; bLo[2 * p][1] = r[1];
            bLo[2 * p + 1][0] = r[2]; bLo[2 * p + 1][1] = r[3];
        }
        #pragma unroll
        for (int mt = 0; mt < 4; ++mt)
            #pragma unroll
            for (int nt = 0; nt < 4; ++nt) {
                mma16816(ac[mt][nt], aHi[mt], bHi[nt]);
                mma16816(ac[mt][nt], aHi[mt], bLo[nt]);
                mma16816(ac[mt][nt], aLo[mt], bHi[nt]);
            }
    }
    __syncthreads();

    float* sR = (float*)smc;
    {
        int rr = lane >> 2;
        int cc = (lane & 3) * 2;
        #pragma unroll
        for (int mt = 0; mt < 4; ++mt)
            #pragma unroll
            for (int nt = 0; nt < 4; ++nt) {
                int r0 = wm + mt * 16 + rr;
                int c = wn + nt * 8 + cc;
                *(float2*)&sR[r0 * 130 + c]       = make_float2(ac[mt][nt][0], ac[mt][nt][1]);
                *(float2*)&sR[(r0 + 8) * 130 + c] = make_float2(ac[mt][nt][2], ac[mt][nt][3]);
            }
    }
    __syncthreads();

    {
        int col = t >> 1;
        int q = t & 1;
        int eb = q * 64;
        float bias = __ldg(be2 + col);
        int cur = sDst[eb];
        float m = sR[eb * 130 + col];
        #pragma unroll 4
        for (int i = 1; i < 64; ++i) {
            int e = eb + i;
            int d = sDst[e];
            float v = sR[e * 130 + col];
            if (d != cur) {
                float mb = m + bias;
                if (mb > 0.f) atomicMax((int*)(agg + (size_t)cur * 128 + col), __float_as_int(mb));
                cur = d; m = v;
            } else {
                m = fmaxf(m, v);
            }
        }
        float mb = m + bias;
        if (mb > 0.f) atomicMax((int*)(agg + (size_t)cur * 128 + col), __float_as_int(mb));
    }
}

// ---------------- pooling ----------------
__global__ void k_zero_pool() {
    int i = blockIdx.x * blockDim.x + threadIdx.x;
    if (i < NG * 128) { d_gmax[i] = 0.f; d_gsum[i] = 0.f; }
    if (i < NG) d_gcnt[i] = 0.f;
}

__global__ void __launch_bounds__(256)
k_pool2(const int* __restrict__ batch, const float* __restrict__ X) {
    int base = blockIdx.x * 128;
    int ch = threadIdx.x & 127;
    int half = threadIdx.x >> 7;
    int cur = -1;
    float vmax = 0.f, vsum = 0.f;
    for (int i = half; i < 128; i += 2) {
        int n = base + i;
        if (n >= NN) break;
        int g = batch[n];
        if (g != cur) {
            if (cur >= 0) {
                atomicAdd(&d_gsum[cur * 128 + ch], vsum);
                if (vmax > 0.f) atomicMax((int*)&d_gmax[cur * 128 + ch], __float_as_int(vmax));
            }
            cur = g; vmax = 0.f; vsum = 0.f;
        }
        float v = X[(size_t)n * 128 + ch];
        vsum += v;
        vmax = fmaxf(vmax, v);
    }
    if (cur >= 0) {
        atomicAdd(&d_gsum[cur * 128 + ch], vsum);
        if (vmax > 0.f) atomicMax((int*)&d_gmax[cur * 128 + ch], __float_as_int(vmax));
    }
    if (threadIdx.x == 0) {
        int c = -1; float cnt = 0.f;
        for (int i = 0; i < 128; ++i) {
            int n = base + i;
            if (n >= NN) break;
            int g = batch[n];
            if (g != c) {
                if (c >= 0) atomicAdd(&d_gcnt[c], cnt);
                c = g; cnt = 0.f;
            }
            cnt += 1.f;
        }
        if (c >= 0) atomicAdd(&d_gcnt[c], cnt);
    }
}

__global__ void k_pool_fin() {
    int t = blockIdx.x * blockDim.x + threadIdx.x;
    if (t >= NG * 256) return;
    int g = t >> 8, c = t & 255;
    float v;
    if (c < 128) v = d_gmax[g * 128 + c];
    else         v = d_gsum[g * 128 + c - 128] / fmaxf(d_gcnt[g], 1.0f);
    d_g[t] = v;
}

// ---------------- head ----------------
__global__ void head_gemm(const float* __restrict__ in, const float* __restrict__ W,
                          const float* __restrict__ b, float* __restrict__ out) {
    __shared__ float srow[256];
    int t = threadIdx.x;
    int g = blockIdx.x;
    srow[t] = in[g * 256 + t];
    __syncthreads();
    float acc = b[t];
    #pragma unroll 8
    for (int k = 0; k < 256; ++k) acc = fmaf(srow[k], W[k * 256 + t], acc);
    out[g * 256 + t] = fmaxf(acc, 0.f);
}

// ---------------- launch ----------------
extern "C" void kernel_launch(void* const* d_in, const int* in_sizes, int n_in,
                              void* d_out, int out_size) {
    const float* nodes   = (const float*)d_in[0];
    const int*   cats    = (const int*)d_in[1];
    const int*   ei      = (const int*)d_in[2];
    const int*   batch   = (const int*)d_in[3];
    const float* cat_emb = (const float*)d_in[4];
    const float* W1  = (const float*)d_in[5];
    const float* b1  = (const float*)d_in[6];
    const float* W2  = (const float*)d_in[7];
    const float* b2  = (const float*)d_in[8];
    const float* W3  = (const float*)d_in[9];
    const float* b3  = (const float*)d_in[10];
    const float* We1 = (const float*)d_in[11];
    const float* be1 = (const float*)d_in[12];
    const float* We2 = (const float*)d_in[13];
    const float* be2 = (const float*)d_in[14];
    const float* Wf1 = (const float*)d_in[15];
    const float* bf1 = (const float*)d_in[16];
    const float* Wf2 = (const float*)d_in[17];
    const float* bf2 = (const float*)d_in[18];
    const int* src = ei;
    const int* dst = ei + NE;
    float* out = (float*)d_out;

    const int MMA_SMEM = 139264;  // 4 x 34816

    cudaFuncSetAttribute(gemm_mma,     cudaFuncAttributeMaxDynamicSharedMemorySize, MMA_SMEM);
    cudaFuncSetAttribute(edge_mlp_mma, cudaFuncAttributeMaxDynamicSharedMemorySize, MMA_SMEM);

    float *bufA, *bufB, *bufC, *x0, *g, *h1;
    __nv_bfloat16 *gwh, *gwl;
    cudaGetSymbolAddress((void**)&bufA, d_bufA);
    cudaGetSymbolAddress((void**)&bufB, d_bufB);
    cudaGetSymbolAddress((void**)&bufC, d_bufC);
    cudaGetSymbolAddress((void**)&x0,   d_x0);
    cudaGetSymbolAddress((void**)&g,    d_g);
    cudaGetSymbolAddress((void**)&h1,   d_h1);
    cudaGetSymbolAddress((void**)&gwh,  d_gWhi);
    cudaGetSymbolAddress((void**)&gwl,  d_gWlo);

    // CSR + norms
    k_init<<<(NN + 255) / 256, 256>>>();
    k_count<<<(NE + 255) / 256, 256>>>(dst);
    k_dinv<<<(NN + 255) / 256, 256>>>();
    k_bsum<<<NB, 256>>>();
    k_bscan<<<1, 256>>>();
    k_escan<<<NB, 256>>>();
    k_scatter<<<(NE + 255) / 256, 256>>>(src, dst);

    // x0 = [nodes | emb]; weight images
    k_embed<<<(NN * 16 + 255) / 256, 256>>>(nodes, cats, cat_emb);
    k_prepw<<<64, 256>>>(We2);
    k_prepw_gen<<<(5 * 16384 + 255) / 256, 256>>>(W1, W2, W3, We1);

    const int gg = (NN + 127) / 128;  // 391
    // GCN 1
    gemm_mma<<<gg, 256, MMA_SMEM>>>(x0, NN, 64, gwh + 0 * WIMG, gwl + 0 * WIMG, nullptr, bufA);
    gcn_agg<<<(NN + 7) / 8, 256>>>(bufA, b1, bufB);
    // GCN 2
    gemm_mma<<<gg, 256, MMA_SMEM>>>(bufB, NN, 128, gwh + 1 * WIMG, gwl + 1 * WIMG, nullptr, bufA);
    gcn_agg<<<(NN + 7) / 8, 256>>>(bufA, b2, bufB);
    // GCN 3
    gemm_mma<<<gg, 256, MMA_SMEM>>>(bufB, NN, 128, gwh + 2 * WIMG, gwl + 2 * WIMG, nullptr, bufA);
    gcn_agg<<<(NN + 7) / 8, 256>>>(bufA, b3, bufC);   // x3 -> bufC

    // EdgeConv precompute: A = x3 @ (We1_top - We1_bot) + be1 ; B = x3 @ We1_bot
    gemm_mma<<<gg, 256, MMA_SMEM>>>(bufC, NN, 128, gwh + 3 * WIMG, gwl + 3 * WIMG, be1, bufA);
    gemm_mma<<<gg, 256, MMA_SMEM>>>(bufC, NN, 128, gwh + 4 * WIMG, gwl + 4 * WIMG, nullptr, bufB);

    // EdgeConv per-edge MLP + segment max via mma.sync
    k_zero<<<(NN * 32 + 255) / 256, 256>>>(bufC, NN * 32);
    edge_mlp_mma<<<NE / 128, 256, MMA_SMEM>>>(bufA, bufB, be2, bufC);

    // pooling
    k_zero_pool<<<(NG * 128 + 255) / 256, 256>>>();
    k_pool2<<<(NN + 127) / 128, 256>>>(batch, bufC);
    k_pool_fin<<<(NG * 256 + 255) / 256, 256>>>();

    // head
    head_gemm<<<NG, 256>>>(g, Wf1, bf1, h1);
    head_gemm<<<NG, 256>>>(h1, Wf2, bf2, out);
}

// round 9
// speedup vs baseline: 2.9242x; 1.0996x over previous
#include <cuda_runtime.h>
#include <cuda_bf16.h>
#include <cstddef>
#include <cstdint>

#define NN 50000
#define NE 800000
#define NG 64
#define NB 196   // ceil(NN/256)

// ---------------- scratch (__device__ globals; no allocation allowed) ----------------
__device__ __align__(16) float d_x0[NN * 64];
__device__ __align__(16) float d_bufA[NN * 128];
__device__ __align__(16) float d_bufB[NN * 128];
__device__ __align__(16) float d_bufC[NN * 128];
__device__ __align__(16) float d_dinv[NN];
__device__ int d_ecnt[NN];
__device__ int d_cursor[NN];
__device__ int d_rowptr[NN + 1];
__device__ int d_bsum[256];
__device__ int d_boff[256];
__device__ int d_csr_src[NE];
__device__ int d_csr_dst[NE];
__device__ __align__(16) float d_csr_norm[NE];
__device__ __align__(16) float d_gmax[NG * 128];
__device__ __align__(16) float d_gsum[NG * 128];
__device__ float d_gcnt[NG];
__device__ __align__(16) float d_g[NG * 256];
__device__ __align__(16) float d_h1[NG * 256];
// prebuilt We2^T bf16 hi/lo images: [n][k] rows, stride 136 elems (272 B)
__device__ __align__(16) __nv_bfloat16 d_Whi[128 * 136];
__device__ __align__(16) __nv_bfloat16 d_Wlo[128 * 136];
// prebuilt node-GEMM weight images: 5 x [128][136]  (W1,W2,W3,Wd=We1t-We1b,Wb=We1b)
__device__ __align__(16) __nv_bfloat16 d_gWhi[5 * 128 * 136];
__device__ __align__(16) __nv_bfloat16 d_gWlo[5 * 128 * 136];

#define WIMG (128 * 136)

// ---------------- mma.sync helpers ----------------
__device__ __forceinline__ uint32_t smem_u32(const void* p) {
    uint32_t a;
    asm("{ .reg .u64 t; cvta.to.shared.u64 t, %1; cvt.u32.u64 %0, t; }" : "=r"(a) : "l"(p));
    return a;
}
__device__ __forceinline__ void ldm_x4(uint32_t* r, uint32_t addr) {
    asm volatile("ldmatrix.sync.aligned.m8n8.x4.shared.b16 {%0,%1,%2,%3}, [%4];"
                 : "=r"(r[0]), "=r"(r[1]), "=r"(r[2]), "=r"(r[3]) : "r"(addr));
}
__device__ __forceinline__ void mma16816(float* d, const uint32_t* a, const uint32_t* b) {
    asm volatile("mma.sync.aligned.m16n8k16.row.col.f32.bf16.bf16.f32 "
                 "{%0,%1,%2,%3}, {%4,%5,%6,%7}, {%8,%9}, {%0,%1,%2,%3};"
                 : "+f"(d[0]), "+f"(d[1]), "+f"(d[2]), "+f"(d[3])
                 : "r"(a[0]), "r"(a[1]), "r"(a[2]), "r"(a[3]), "r"(b[0]), "r"(b[1]));
}
__device__ __forceinline__ void split_pack(float v0, float v1, uint32_t& hi, uint32_t& lo) {
    __nv_bfloat16 h0 = __float2bfloat16(v0), h1 = __float2bfloat16(v1);
    __nv_bfloat16 l0 = __float2bfloat16(v0 - __bfloat162float(h0));
    __nv_bfloat16 l1 = __float2bfloat16(v1 - __bfloat162float(h1));
    hi = (uint32_t)__bfloat16_as_ushort(h0) | ((uint32_t)__bfloat16_as_ushort(h1) << 16);
    lo = (uint32_t)__bfloat16_as_ushort(l0) | ((uint32_t)__bfloat16_as_ushort(l1) << 16);
}

// ---------------- graph preprocessing ----------------
__global__ void k_init() {
    int i = blockIdx.x * blockDim.x + threadIdx.x;
    if (i < NN) { d_ecnt[i] = 0; d_cursor[i] = 0; }
}

__global__ void k_count(const int* __restrict__ dst) {
    int e = blockIdx.x * blockDim.x + threadIdx.x;
    if (e < NE) atomicAdd(&d_ecnt[dst[e]], 1);
}

__global__ void k_dinv() {
    int i = blockIdx.x * blockDim.x + threadIdx.x;
    if (i < NN) d_dinv[i] = rsqrtf((float)d_ecnt[i] + 1.0f);
}

__global__ void k_bsum() {
    __shared__ int s[256];
    int t = threadIdx.x;
    int i = blockIdx.x * 256 + t;
    s[t] = (i < NN) ? d_ecnt[i] : 0;
    __syncthreads();
    #pragma unroll
    for (int off = 128; off > 0; off >>= 1) {
        if (t < off) s[t] += s[t + off];
        __syncthreads();
    }
    if (t == 0) d_bsum[blockIdx.x] = s[0];
}

__global__ void k_bscan() {
    __shared__ int s[256];
    int t = threadIdx.x;
    int v0 = (t < NB) ? d_bsum[t] : 0;
    s[t] = v0;
    __syncthreads();
    #pragma unroll
    for (int off = 1; off < 256; off <<= 1) {
        int v = (t >= off) ? s[t - off] : 0;
        __syncthreads();
        s[t] += v;
        __syncthreads();
    }
    d_boff[t] = s[t] - v0;
}

__global__ void k_escan() {
    __shared__ int s[256];
    int t = threadIdx.x;
    int i = blockIdx.x * 256 + t;
    int v0 = (i < NN) ? d_ecnt[i] : 0;
    s[t] = v0;
    __syncthreads();
    #pragma unroll
    for (int off = 1; off < 256; off <<= 1) {
        int v = (t >= off) ? s[t - off] : 0;
        __syncthreads();
        s[t] += v;
        __syncthreads();
    }
    if (i < NN) d_rowptr[i + 1] = d_boff[blockIdx.x] + s[t];
    if (i == 0) d_rowptr[0] = 0;
}

__global__ void k_scatter(const int* __restrict__ src, const int* __restrict__ dst) {
    int e = blockIdx.x * blockDim.x + threadIdx.x;
    if (e >= NE) return;
    int s = src[e], d = dst[e];
    int pos = d_rowptr[d] + atomicAdd(&d_cursor[d], 1);
    d_csr_src[pos] = s;
    d_csr_dst[pos] = d;
    d_csr_norm[pos] = d_dinv[s] * d_dinv[d];
}

// ---------------- x0 = [nodes | cat_emb[cats]] ----------------
__global__ void k_embed(const float* __restrict__ nodes, const int* __restrict__ cats,
                        const float* __restrict__ emb) {
    int t = blockIdx.x * blockDim.x + threadIdx.x;
    if (t >= NN * 16) return;
    int node = t >> 4, j = t & 15;
    float4 v;
    if (j < 8) v = ((const float4*)nodes)[node * 8 + j];
    else       v = ((const float4*)emb)[(size_t)cats[node] * 8 + (j - 8)];
    ((float4*)d_x0)[node * 16 + j] = v;
}

// ---------------- prebuild We2^T hi/lo image ([n][k], stride 136) ----------------
__global__ void k_prepw(const float* __restrict__ We2) {
    int i = blockIdx.x * blockDim.x + threadIdx.x;
    if (i >= 16384) return;
    int n = i >> 7, k = i & 127;
    float w = We2[k * 128 + n];
    __nv_bfloat16 h = __float2bfloat16(w);
    __nv_bfloat16 l = __float2bfloat16(w - __bfloat162float(h));
    d_Whi[n * 136 + k] = h;
    d_Wlo[n * 136 + k] = l;
}

// ---------------- prebuild node-GEMM weight images ----------------
__global__ void k_prepw_gen(const float* __restrict__ W1, const float* __restrict__ W2,
                            const float* __restrict__ W3, const float* __restrict__ We1) {
    int i = blockIdx.x * blockDim.x + threadIdx.x;
    if (i >= 5 * 16384) return;
    int img = i >> 14;
    int idx = i & 16383;
    int n = idx >> 7, k = idx & 127;
    float w;
    if (img == 0) {
        if (k >= 64) return;
        w = W1[k * 128 + n];
    } else if (img == 1) {
        w = W2[k * 128 + n];
    } else if (img == 2) {
        w = W3[k * 128 + n];
    } else if (img == 3) {
        w = We1[k * 128 + n] - We1[(k + 128) * 128 + n];
    } else {
        w = We1[(k + 128) * 128 + n];
    }
    __nv_bfloat16 h = __float2bfloat16(w);
    __nv_bfloat16 l = __float2bfloat16(w - __bfloat162float(h));
    d_gWhi[img * WIMG + n * 136 + k] = h;
    d_gWlo[img * WIMG + n * 136 + k] = l;
}

// shared smem layout for 64-row MMA blocks
#define XHI 0u
#define XLO 17408u
#define WHI 34816u
#define WLO 69632u
#define MMA_SMEM 104448

// ---------------- node GEMM via mma.sync bf16 3-split ----------------
// Y[M,128] = X[M,Kin] @ W  (+bias). 64 rows/block, 256 threads (8 warps), 2 CTAs/SM.
__global__ void __launch_bounds__(256, 2)
gemm_mma(const float* __restrict__ X, int M, int Kin,
         const __nv_bfloat16* __restrict__ gWhi, const __nv_bfloat16* __restrict__ gWlo,
         const float* __restrict__ bias, float* __restrict__ Y) {
    extern __shared__ __align__(16) char smc[];
    const int t = threadIdx.x;
    const int wid = t >> 5;
    const int lane = t & 31;
    const int row0 = blockIdx.x * 64;
    const uint32_t sb = smem_u32(smc);

    // async copy W images (69632 B total)
    {
        const uint4* gh = (const uint4*)gWhi;
        const uint4* gl = (const uint4*)gWlo;
        for (int i = t; i < 2176; i += 256) {
            asm volatile("cp.async.cg.shared.global [%0], [%1], 16;"
                         :: "r"(sb + WHI + i * 16), "l"(gh + i));
            asm volatile("cp.async.cg.shared.global [%0], [%1], 16;"
                         :: "r"(sb + WLO + i * 16), "l"(gl + i));
        }
        asm volatile("cp.async.commit_group;");
    }

    // gather X rows -> XHI/XLO [r][k], row stride 272 B; 4 threads per row
    {
        int r = t & 63, hf = t >> 6;        // hf in 0..3
        int gr = row0 + r;
        const float4* Xr = (const float4*)(X + (size_t)gr * Kin);
        int q = Kin >> 4;                   // float4 segs per quarter (4 or 8)
        char* pHi = smc + XHI;
        char* pLo = smc + XLO;
        uint32_t rowb = (uint32_t)r * 272u;
        if (gr < M) {
            #pragma unroll 4
            for (int s = hf * q; s < (hf + 1) * q; ++s) {
                float4 v = __ldg(Xr + s);
                uint2 hv, lv;
                split_pack(v.x, v.y, hv.x, lv.x);
                split_pack(v.z, v.w, hv.y, lv.y);
                uint32_t off = rowb + (uint32_t)s * 8u;
                *(uint2*)(pHi + off) = hv;
                *(uint2*)(pLo + off) = lv;
            }
        } else {
            for (int s = hf * q; s < (hf + 1) * q; ++s) {
                uint32_t off = rowb + (uint32_t)s * 8u;
                *(uint2*)(pHi + off) = make_uint2(0u, 0u);
                *(uint2*)(pLo + off) = make_uint2(0u, 0u);
            }
        }
    }
    asm volatile("cp.async.wait_group 0;" ::: "memory");
    __syncthreads();

    const int wm = (wid & 1) * 32;
    const int wn = (wid >> 1) * 32;
    const int lid8 = lane & 7;
    const int grp = lane >> 3;

    uint32_t aAddrHi[2], aAddrLo[2];
    {
        uint32_t row = (uint32_t)(wm + (grp & 1) * 8 + lid8);
        uint32_t col = (uint32_t)((grp >> 1) * 8);
        #pragma unroll
        for (int mt = 0; mt < 2; ++mt) {
            uint32_t byteOff = (row + mt * 16) * 272u + col * 2u;
            aAddrHi[mt] = sb + XHI + byteOff;
            aAddrLo[mt] = sb + XLO + byteOff;
        }
    }
    uint32_t bAddrHi[2], bAddrLo[2];
    {
        uint32_t row = (uint32_t)(wn + (grp >> 1) * 8 + lid8);
        uint32_t col = (uint32_t)((grp & 1) * 8);
        #pragma unroll
        for (int p = 0; p < 2; ++p) {
            uint32_t byteOff = (row + p * 16) * 272u + col * 2u;
            bAddrHi[p] = sb + WHI + byteOff;
            bAddrLo[p] = sb + WLO + byteOff;
        }
    }

    float ac[2][4][4];
    #pragma unroll
    for (int i = 0; i < 2; i++)
        #pragma unroll
        for (int j = 0; j < 4; j++)
            #pragma unroll
            for (int q2 = 0; q2 < 4; q2++) ac[i][j][q2] = 0.f;

    const int nkt = Kin >> 4;
    for (int kt = 0; kt < nkt; ++kt) {
        uint32_t kb = kt * 32u;
        uint32_t aHi[2][4], aLo[2][4];
        uint32_t bHi[4][2], bLo[4][2];
        #pragma unroll
        for (int mt = 0; mt < 2; ++mt) {
            ldm_x4(aHi[mt], aAddrHi[mt] + kb);
            ldm_x4(aLo[mt], aAddrLo[mt] + kb);
        }
        #pragma unroll
        for (int p = 0; p < 2; ++p) {
            uint32_t r[4];
            ldm_x4(r, bAddrHi[p] + kb);
            bHi[2 * p][0] = r[0]; bHi[2 * p][1] = r[1];
            bHi[2 * p + 1][0] = r[2]; bHi[2 * p + 1][1] = r[3];
            ldm_x4(r, bAddrLo[p] + kb);
            bLo[2 * p][0] = r[0]; bLo[2 * p][1] = r[1];
            bLo[2 * p + 1][0] = r[2]; bLo[2 * p + 1][1] = r[3];
        }
        #pragma unroll
        for (int mt = 0; mt < 2; ++mt)
            #pragma unroll
            for (int nt = 0; nt < 4; ++nt) {
                mma16816(ac[mt][nt], aHi[mt], bHi[nt]);
                mma16816(ac[mt][nt], aHi[mt], bLo[nt]);
                mma16816(ac[mt][nt], aLo[mt], bHi[nt]);
            }
    }

    // epilogue: write D (+bias) to Y
    {
        int rr = lane >> 2;
        int cc = (lane & 3) * 2;
        #pragma unroll
        for (int nt = 0; nt < 4; ++nt) {
            int c = wn + nt * 8 + cc;
            float b0 = bias ? __ldg(bias + c)     : 0.f;
            float b1 = bias ? __ldg(bias + c + 1) : 0.f;
            #pragma unroll
            for (int mt = 0; mt < 2; ++mt) {
                int r0 = wm + mt * 16 + rr;
                int gr0 = row0 + r0;
                int gr1 = gr0 + 8;
                if (gr0 < M)
                    *(float2*)&Y[(size_t)gr0 * 128 + c] =
                        make_float2(ac[mt][nt][0] + b0, ac[mt][nt][1] + b1);
                if (gr1 < M)
                    *(float2*)&Y[(size_t)gr1 * 128 + c] =
                        make_float2(ac[mt][nt][2] + b0, ac[mt][nt][3] + b1);
            }
        }
    }
}

// ---------------- GCN aggregation ----------------
__global__ void gcn_agg(const float* __restrict__ H, const float* __restrict__ bias,
                        float* __restrict__ out) {
    int warp = threadIdx.x >> 5;
    int lane = threadIdx.x & 31;
    int node = blockIdx.x * 8 + warp;
    if (node >= NN) return;
    float dv = d_dinv[node];
    float sn = dv * dv;
    float4 acc = ((const float4*)H)[node * 32 + lane];
    acc.x *= sn; acc.y *= sn; acc.z *= sn; acc.w *= sn;
    int beg = d_rowptr[node], end = d_rowptr[node + 1];
    int e = beg;
    for (; e + 3 < end; e += 4) {
        int s0 = d_csr_src[e],     s1 = d_csr_src[e + 1];
        int s2 = d_csr_src[e + 2], s3 = d_csr_src[e + 3];
        float n0 = d_csr_norm[e],     n1 = d_csr_norm[e + 1];
        float n2 = d_csr_norm[e + 2], n3 = d_csr_norm[e + 3];
        float4 h0 = ((const float4*)H)[s0 * 32 + lane];
        float4 h1 = ((const float4*)H)[s1 * 32 + lane];
        float4 h2 = ((const float4*)H)[s2 * 32 + lane];
        float4 h3 = ((const float4*)H)[s3 * 32 + lane];
        acc.x = fmaf(h0.x, n0, acc.x); acc.y = fmaf(h0.y, n0, acc.y);
        acc.z = fmaf(h0.z, n0, acc.z); acc.w = fmaf(h0.w, n0, acc.w);
        acc.x = fmaf(h1.x, n1, acc.x); acc.y = fmaf(h1.y, n1, acc.y);
        acc.z = fmaf(h1.z, n1, acc.z); acc.w = fmaf(h1.w, n1, acc.w);
        acc.x = fmaf(h2.x, n2, acc.x); acc.y = fmaf(h2.y, n2, acc.y);
        acc.z = fmaf(h2.z, n2, acc.z); acc.w = fmaf(h2.w, n2, acc.w);
        acc.x = fmaf(h3.x, n3, acc.x); acc.y = fmaf(h3.y, n3, acc.y);
        acc.z = fmaf(h3.z, n3, acc.z); acc.w = fmaf(h3.w, n3, acc.w);
    }
    for (; e < end; ++e) {
        int s = d_csr_src[e];
        float nm = d_csr_norm[e];
        float4 h = ((const float4*)H)[s * 32 + lane];
        acc.x = fmaf(h.x, nm, acc.x); acc.y = fmaf(h.y, nm, acc.y);
        acc.z = fmaf(h.z, nm, acc.z); acc.w = fmaf(h.w, nm, acc.w);
    }
    float4 b = ((const float4*)bias)[lane];
    float4 r;
    r.x = fmaxf(acc.x + b.x, 0.f);
    r.y = fmaxf(acc.y + b.y, 0.f);
    r.z = fmaxf(acc.z + b.z, 0.f);
    r.w = fmaxf(acc.w + b.w, 0.f);
    ((float4*)out)[node * 32 + lane] = r;
}

__global__ void k_zero(float* __restrict__ p, int n4) {
    int i = blockIdx.x * blockDim.x + threadIdx.x;
    if (i < n4) ((float4*)p)[i] = make_float4(0.f, 0.f, 0.f, 0.f);
}

// ---------------- EdgeConv via mma.sync bf16 3-MMA split ----------------
// 64 edges/block, 256 threads, 2 CTAs/SM.
__global__ void __launch_bounds__(256, 2)
edge_mlp_mma(const float* __restrict__ A, const float* __restrict__ Bm,
             const float* __restrict__ be2, float* __restrict__ agg) {
    extern __shared__ __align__(16) char smc[];
    __shared__ int sDst[64];
    __shared__ int sSrc[64];

    const int t = threadIdx.x;
    const int wid = t >> 5;
    const int lane = t & 31;
    const int e0 = blockIdx.x * 64;
    const uint32_t sb = smem_u32(smc);

    if (t < 64) { sDst[t] = d_csr_dst[e0 + t]; sSrc[t] = d_csr_src[e0 + t]; }

    {
        const uint4* gh = (const uint4*)d_Whi;
        const uint4* gl = (const uint4*)d_Wlo;
        for (int i = t; i < 2176; i += 256) {
            asm volatile("cp.async.cg.shared.global [%0], [%1], 16;"
                         :: "r"(sb + WHI + i * 16), "l"(gh + i));
            asm volatile("cp.async.cg.shared.global [%0], [%1], 16;"
                         :: "r"(sb + WLO + i * 16), "l"(gl + i));
        }
        asm volatile("cp.async.commit_group;");
    }
    __syncthreads();

    // gather relu(A[dst]+B[src]) -> XHI/XLO [e][k]; 4 threads per edge
    {
        int e = t & 63, hf = t >> 6;
        int d = sDst[e], s = sSrc[e];
        const float4* Ad = (const float4*)(A  + (size_t)d * 128);
        const float4* Bs = (const float4*)(Bm + (size_t)s * 128);
        uint32_t rowb = (uint32_t)e * 272u;
        char* pHi = smc + XHI;
        char* pLo = smc + XLO;
        #pragma unroll 8
        for (int seg = hf * 8; seg < hf * 8 + 8; ++seg) {
            float4 av = __ldg(Ad + seg);
            float4 bv = __ldg(Bs + seg);
            float v0 = fmaxf(av.x + bv.x, 0.f);
            float v1 = fmaxf(av.y + bv.y, 0.f);
            float v2 = fmaxf(av.z + bv.z, 0.f);
            float v3 = fmaxf(av.w + bv.w, 0.f);
            uint2 hv, lv;
            split_pack(v0, v1, hv.x, lv.x);
            split_pack(v2, v3, hv.y, lv.y);
            uint32_t off = rowb + (uint32_t)seg * 8u;
            *(uint2*)(pHi + off) = hv;
            *(uint2*)(pLo + off) = lv;
        }
    }
    asm volatile("cp.async.wait_group 0;" ::: "memory");
    __syncthreads();

    const int wm = (wid & 1) * 32;
    const int wn = (wid >> 1) * 32;
    const int lid8 = lane & 7;
    const int grp = lane >> 3;

    uint32_t aAddrHi[2], aAddrLo[2];
    {
        uint32_t row = (uint32_t)(wm + (grp & 1) * 8 + lid8);
        uint32_t col = (uint32_t)((grp >> 1) * 8);
        #pragma unroll
        for (int mt = 0; mt < 2; ++mt) {
            uint32_t byteOff = (row + mt * 16) * 272u + col * 2u;
            aAddrHi[mt] = sb + XHI + byteOff;
            aAddrLo[mt] = sb + XLO + byteOff;
        }
    }
    uint32_t bAddrHi[2], bAddrLo[2];
    {
        uint32_t row = (uint32_t)(wn + (grp >> 1) * 8 + lid8);
        uint32_t col = (uint32_t)((grp & 1) * 8);
        #pragma unroll
        for (int p = 0; p < 2; ++p) {
            uint32_t byteOff = (row + p * 16) * 272u + col * 2u;
            bAddrHi[p] = sb + WHI + byteOff;
            bAddrLo[p] = sb + WLO + byteOff;
        }
    }

    float ac[2][4][4];
    #pragma unroll
    for (int i = 0; i < 2; i++)
        #pragma unroll
        for (int j = 0; j < 4; j++)
            #pragma unroll
            for (int q2 = 0; q2 < 4; q2++) ac[i][j][q2] = 0.f;

    #pragma unroll
    for (int kt = 0; kt < 8; ++kt) {
        uint32_t kb = kt * 32u;
        uint32_t aHi[2][4], aLo[2][4];
        uint32_t bHi[4][2], bLo[4][2];
        #pragma unroll
        for (int mt = 0; mt < 2; ++mt) {
            ldm_x4(aHi[mt], aAddrHi[mt] + kb);
            ldm_x4(aLo[mt], aAddrLo[mt] + kb);
        }
        #pragma unroll
        for (int p = 0; p < 2; ++p) {
            uint32_t r[4];
            ldm_x4(r, bAddrHi[p] + kb);
            bHi[2 * p][0] = r[0]; bHi[2 * p][1] = r[1];
            bHi[2 * p + 1][0] = r[2]; bHi[2 * p + 1][1] = r[3];
            ldm_x4(r, bAddrLo[p] + kb);
            bLo[2 * p][0] = r[0]; bLo[2 * p][1] = r[1];
            bLo[2 * p + 1][0] = r[2]; bLo[2 * p + 1][1] = r[3];
        }
        #pragma unroll
        for (int mt = 0; mt < 2; ++mt)
            #pragma unroll
            for (int nt = 0; nt < 4; ++nt) {
                mma16816(ac[mt][nt], aHi[mt], bHi[nt]);
                mma16816(ac[mt][nt], aHi[mt], bLo[nt]);
                mma16816(ac[mt][nt], aLo[mt], bHi[nt]);
            }
    }
    __syncthreads();

    // stage D into sR[e][130] (overlays XHI/XLO: 64*130*4 = 33280 <= 34816)
    float* sR = (float*)smc;
    {
        int rr = lane >> 2;
        int cc = (lane & 3) * 2;
        #pragma unroll
        for (int mt = 0; mt < 2; ++mt)
            #pragma unroll
            for (int nt = 0; nt < 4; ++nt) {
                int r0 = wm + mt * 16 + rr;
                int c = wn + nt * 8 + cc;
                *(float2*)&sR[r0 * 130 + c]       = make_float2(ac[mt][nt][0], ac[mt][nt][1]);
                *(float2*)&sR[(r0 + 8) * 130 + c] = make_float2(ac[mt][nt][2], ac[mt][nt][3]);
            }
    }
    __syncthreads();

    // per-(col, half) dst-run reduction; bias added AFTER max
    {
        int col = t >> 1;
        int q = t & 1;
        int eb = q * 32;
        float bias = __ldg(be2 + col);
        int cur = sDst[eb];
        float m = sR[eb * 130 + col];
        #pragma unroll 4
        for (int i = 1; i < 32; ++i) {
            int e = eb + i;
            int d = sDst[e];
            float v = sR[e * 130 + col];
            if (d != cur) {
                float mb = m + bias;
                if (mb > 0.f) atomicMax((int*)(agg + (size_t)cur * 128 + col), __float_as_int(mb));
                cur = d; m = v;
            } else {
                m = fmaxf(m, v);
            }
        }
        float mb = m + bias;
        if (mb > 0.f) atomicMax((int*)(agg + (size_t)cur * 128 + col), __float_as_int(mb));
    }
}

// ---------------- pooling ----------------
__global__ void k_zero_pool() {
    int i = blockIdx.x * blockDim.x + threadIdx.x;
    if (i < NG * 128) { d_gmax[i] = 0.f; d_gsum[i] = 0.f; }
    if (i < NG) d_gcnt[i] = 0.f;
}

__global__ void __launch_bounds__(256)
k_pool2(const int* __restrict__ batch, const float* __restrict__ X) {
    int base = blockIdx.x * 128;
    int ch = threadIdx.x & 127;
    int half = threadIdx.x >> 7;
    int cur = -1;
    float vmax = 0.f, vsum = 0.f;
    for (int i = half; i < 128; i += 2) {
        int n = base + i;
        if (n >= NN) break;
        int g = batch[n];
        if (g != cur) {
            if (cur >= 0) {
                atomicAdd(&d_gsum[cur * 128 + ch], vsum);
                if (vmax > 0.f) atomicMax((int*)&d_gmax[cur * 128 + ch], __float_as_int(vmax));
            }
            cur = g; vmax = 0.f; vsum = 0.f;
        }
        float v = X[(size_t)n * 128 + ch];
        vsum += v;
        vmax = fmaxf(vmax, v);
    }
    if (cur >= 0) {
        atomicAdd(&d_gsum[cur * 128 + ch], vsum);
        if (vmax > 0.f) atomicMax((int*)&d_gmax[cur * 128 + ch], __float_as_int(vmax));
    }
    if (threadIdx.x == 0) {
        int c = -1; float cnt = 0.f;
        for (int i = 0; i < 128; ++i) {
            int n = base + i;
            if (n >= NN) break;
            int g = batch[n];
            if (g != c) {
                if (c >= 0) atomicAdd(&d_gcnt[c], cnt);
                c = g; cnt = 0.f;
            }
            cnt += 1.f;
        }
        if (c >= 0) atomicAdd(&d_gcnt[c], cnt);
    }
}

__global__ void k_pool_fin() {
    int t = blockIdx.x * blockDim.x + threadIdx.x;
    if (t >= NG * 256) return;
    int g = t >> 8, c = t & 255;
    float v;
    if (c < 128) v = d_gmax[g * 128 + c];
    else         v = d_gsum[g * 128 + c - 128] / fmaxf(d_gcnt[g], 1.0f);
    d_g[t] = v;
}

// ---------------- head ----------------
__global__ void head_gemm(const float* __restrict__ in, const float* __restrict__ W,
                          const float* __restrict__ b, float* __restrict__ out) {
    __shared__ float srow[256];
    int t = threadIdx.x;
    int g = blockIdx.x;
    srow[t] = in[g * 256 + t];
    __syncthreads();
    float acc = b[t];
    #pragma unroll 8
    for (int k = 0; k < 256; ++k) acc = fmaf(srow[k], W[k * 256 + t], acc);
    out[g * 256 + t] = fmaxf(acc, 0.f);
}

// ---------------- launch ----------------
extern "C" void kernel_launch(void* const* d_in, const int* in_sizes, int n_in,
                              void* d_out, int out_size) {
    const float* nodes   = (const float*)d_in[0];
    const int*   cats    = (const int*)d_in[1];
    const int*   ei      = (const int*)d_in[2];
    const int*   batch   = (const int*)d_in[3];
    const float* cat_emb = (const float*)d_in[4];
    const float* W1  = (const float*)d_in[5];
    const float* b1  = (const float*)d_in[6];
    const float* W2  = (const float*)d_in[7];
    const float* b2  = (const float*)d_in[8];
    const float* W3  = (const float*)d_in[9];
    const float* b3  = (const float*)d_in[10];
    const float* We1 = (const float*)d_in[11];
    const float* be1 = (const float*)d_in[12];
    const float* We2 = (const float*)d_in[13];
    const float* be2 = (const float*)d_in[14];
    const float* Wf1 = (const float*)d_in[15];
    const float* bf1 = (const float*)d_in[16];
    const float* Wf2 = (const float*)d_in[17];
    const float* bf2 = (const float*)d_in[18];
    const int* src = ei;
    const int* dst = ei + NE;
    float* out = (float*)d_out;

    cudaFuncSetAttribute(gemm_mma,     cudaFuncAttributeMaxDynamicSharedMemorySize, MMA_SMEM);
    cudaFuncSetAttribute(edge_mlp_mma, cudaFuncAttributeMaxDynamicSharedMemorySize, MMA_SMEM);

    float *bufA, *bufB, *bufC, *x0, *g, *h1;
    __nv_bfloat16 *gwh, *gwl;
    cudaGetSymbolAddress((void**)&bufA, d_bufA);
    cudaGetSymbolAddress((void**)&bufB, d_bufB);
    cudaGetSymbolAddress((void**)&bufC, d_bufC);
    cudaGetSymbolAddress((void**)&x0,   d_x0);
    cudaGetSymbolAddress((void**)&g,    d_g);
    cudaGetSymbolAddress((void**)&h1,   d_h1);
    cudaGetSymbolAddress((void**)&gwh,  d_gWhi);
    cudaGetSymbolAddress((void**)&gwl,  d_gWlo);

    // CSR + norms
    k_init<<<(NN + 255) / 256, 256>>>();
    k_count<<<(NE + 255) / 256, 256>>>(dst);
    k_dinv<<<(NN + 255) / 256, 256>>>();
    k_bsum<<<NB, 256>>>();
    k_bscan<<<1, 256>>>();
    k_escan<<<NB, 256>>>();
    k_scatter<<<(NE + 255) / 256, 256>>>(src, dst);

    // x0 = [nodes | emb]; weight images
    k_embed<<<(NN * 16 + 255) / 256, 256>>>(nodes, cats, cat_emb);
    k_prepw<<<64, 256>>>(We2);
    k_prepw_gen<<<(5 * 16384 + 255) / 256, 256>>>(W1, W2, W3, We1);

    const int gg = (NN + 63) / 64;  // 782
    // GCN 1
    gemm_mma<<<gg, 256, MMA_SMEM>>>(x0, NN, 64, gwh + 0 * WIMG, gwl + 0 * WIMG, nullptr, bufA);
    gcn_agg<<<(NN + 7) / 8, 256>>>(bufA, b1, bufB);
    // GCN 2
    gemm_mma<<<gg, 256, MMA_SMEM>>>(bufB, NN, 128, gwh + 1 * WIMG, gwl + 1 * WIMG, nullptr, bufA);
    gcn_agg<<<(NN + 7) / 8, 256>>>(bufA, b2, bufB);
    // GCN 3
    gemm_mma<<<gg, 256, MMA_SMEM>>>(bufB, NN, 128, gwh + 2 * WIMG, gwl + 2 * WIMG, nullptr, bufA);
    gcn_agg<<<(NN + 7) / 8, 256>>>(bufA, b3, bufC);   // x3 -> bufC

    // EdgeConv precompute: A = x3 @ (We1_top - We1_bot) + be1 ; B = x3 @ We1_bot
    gemm_mma<<<gg, 256, MMA_SMEM>>>(bufC, NN, 128, gwh + 3 * WIMG, gwl + 3 * WIMG, be1, bufA);
    gemm_mma<<<gg, 256, MMA_SMEM>>>(bufC, NN, 128, gwh + 4 * WIMG, gwl + 4 * WIMG, nullptr, bufB);

    // EdgeConv per-edge MLP + segment max via mma.sync
    k_zero<<<(NN * 32 + 255) / 256, 256>>>(bufC, NN * 32);
    edge_mlp_mma<<<NE / 64, 256, MMA_SMEM>>>(bufA, bufB, be2, bufC);

    // pooling
    k_zero_pool<<<(NG * 128 + 255) / 256, 256>>>();
    k_pool2<<<(NN + 127) / 128, 256>>>(batch, bufC);
    k_pool_fin<<<(NG * 256 + 255) / 256, 256>>>();

    // head
    head_gemm<<<NG, 256>>>(g, Wf1, bf1, h1);
    head_gemm<<<NG, 256>>>(h1, Wf2, bf2, out);
}